// round 1
// baseline (speedup 1.0000x reference)
#include <cuda_runtime.h>
#include <cuda_bf16.h>

// ---------------- problem constants ----------------
#define BATCH   32
#define S_LEN   729
#define EMB     1152
#define NH      16
#define HD      72
#define QKV_N   (3 * EMB)          // 3456
#define ROWS    (BATCH * S_LEN)    // 23328
#define SCALE_F 0.11785113019775792f  // 72^-0.5

// ---------------- scratch (no cudaMalloc allowed) ----------------
__device__ float g_qkv[(size_t)ROWS * QKV_N];   // ~322 MB
__device__ float g_att[(size_t)ROWS * EMB];     // ~107 MB

// ---------------- tiled fp32 GEMM with bias ----------------
// C[M,N] = A[M,K] @ B[K,N] + bias[N]; A,B,C row-major. N%128==0, K%16==0.
#define BM 128
#define BN 128
#define BKK 16

__global__ __launch_bounds__(256) void sgemm_bias(
    const float* __restrict__ A, const float* __restrict__ B,
    const float* __restrict__ bias, float* __restrict__ C,
    int M, int N, int K)
{
    __shared__ float As[BKK][BM];   // transposed A tile
    __shared__ float Bs[BKK][BN];

    const int tid   = threadIdx.x;
    const int crow0 = blockIdx.y * BM;
    const int ccol0 = blockIdx.x * BN;
    const int tr = (tid >> 4) << 3;   // 0..120 step 8
    const int tc = (tid & 15) << 3;   // 0..120 step 8

    float acc[8][8];
    #pragma unroll
    for (int i = 0; i < 8; i++)
        #pragma unroll
        for (int j = 0; j < 8; j++) acc[i][j] = 0.f;

    const float* Ab = A + (long)crow0 * K;
    const float* Bb = B + ccol0;

    for (int k0 = 0; k0 < K; k0 += BKK) {
        // A tile: 128x16 = 512 float4, 2 per thread, store transposed
        #pragma unroll
        for (int i = 0; i < 2; i++) {
            int f  = tid + i * 256;
            int r  = f >> 2;
            int c4 = (f & 3) << 2;
            float4 v = make_float4(0.f, 0.f, 0.f, 0.f);
            if (crow0 + r < M)
                v = *reinterpret_cast<const float4*>(Ab + (long)r * K + k0 + c4);
            As[c4 + 0][r] = v.x;
            As[c4 + 1][r] = v.y;
            As[c4 + 2][r] = v.z;
            As[c4 + 3][r] = v.w;
        }
        // B tile: 16x128 = 512 float4, 2 per thread
        #pragma unroll
        for (int i = 0; i < 2; i++) {
            int f = tid + i * 256;
            int r = f >> 5;
            int c = (f & 31) << 2;
            float4 v = *reinterpret_cast<const float4*>(Bb + (long)(k0 + r) * N + c);
            *reinterpret_cast<float4*>(&Bs[r][c]) = v;
        }
        __syncthreads();

        #pragma unroll
        for (int k = 0; k < BKK; k++) {
            float ra[8], rb[8];
            *reinterpret_cast<float4*>(&ra[0]) = *reinterpret_cast<const float4*>(&As[k][tr]);
            *reinterpret_cast<float4*>(&ra[4]) = *reinterpret_cast<const float4*>(&As[k][tr + 4]);
            *reinterpret_cast<float4*>(&rb[0]) = *reinterpret_cast<const float4*>(&Bs[k][tc]);
            *reinterpret_cast<float4*>(&rb[4]) = *reinterpret_cast<const float4*>(&Bs[k][tc + 4]);
            #pragma unroll
            for (int i = 0; i < 8; i++)
                #pragma unroll
                for (int j = 0; j < 8; j++)
                    acc[i][j] += ra[i] * rb[j];
        }
        __syncthreads();
    }

    #pragma unroll
    for (int i = 0; i < 8; i++) {
        int r = crow0 + tr + i;
        if (r >= M) break;
        #pragma unroll
        for (int j = 0; j < 8; j += 4) {
            int c = ccol0 + tc + j;
            float4 bv = *reinterpret_cast<const float4*>(bias + c);
            float4 o;
            o.x = acc[i][j + 0] + bv.x;
            o.y = acc[i][j + 1] + bv.y;
            o.z = acc[i][j + 2] + bv.z;
            o.w = acc[i][j + 3] + bv.w;
            *reinterpret_cast<float4*>(C + (long)r * N + c) = o;
        }
    }
}

// ---------------- flash-style attention ----------------
// qkv layout: row-major [ROWS, 3456]; q at col h*72, k at 1152+h*72, v at 2304+h*72
// out: [ROWS, 1152] with head h at col h*72 (un-transposed naturally).
#define BQ   64
#define BKV  64
#define NKT  12          // ceil(729/64)
#define HDP  73          // padded row stride in smem (bank-conflict mitigation)
#define SSP  (BKV + 1)   // 65

// smem plan (floats): Qs[64*73] Ks[64*73] Vs[64*73] Ss[64*65] m[64] l[64] r[64]
#define ATTN_SMEM_FLOATS (3 * BQ * HDP + BQ * SSP + 3 * BQ)
#define ATTN_SMEM_BYTES  (ATTN_SMEM_FLOATS * 4)

__global__ __launch_bounds__(256) void attn_kernel(
    const float* __restrict__ qkv, float* __restrict__ out)
{
    extern __shared__ float sm[];
    float* Qs  = sm;
    float* Ks  = Qs + BQ * HDP;
    float* Vs  = Ks + BKV * HDP;
    float* Ss  = Vs + BKV * HDP;
    float* m_s = Ss + BQ * SSP;
    float* l_s = m_s + BQ;
    float* r_s = l_s + BQ;

    const int tid = threadIdx.x;
    const int qt  = blockIdx.x;        // 0..11
    const int bh  = blockIdx.y;        // 0..511
    const int b   = bh >> 4;
    const int h   = bh & 15;
    const long rowbase = (long)b * S_LEN;
    const int  q0 = qt * BQ;

    const float* qp = qkv + h * HD;
    const float* kp = qkv + EMB + h * HD;
    const float* vp = qkv + 2 * EMB + h * HD;

    // load Q tile
    for (int i = tid; i < BQ * HD; i += 256) {
        int q = i / HD, d = i - q * HD;
        int s = q0 + q;
        Qs[q * HDP + d] = (s < S_LEN) ? qp[(rowbase + s) * (long)QKV_N + d] : 0.f;
    }
    if (tid < BQ) { m_s[tid] = -1e30f; l_s[tid] = 0.f; }

    // PV accumulators: 2 queries x 9 dims per thread
    const int tqp = tid >> 3;      // 0..31 -> queries 2*tqp, 2*tqp+1
    const int tdg = tid & 7;       // 0..7  -> dims tdg*9 .. +8
    const int d0  = tdg * 9;
    float acc0[9], acc1[9];
    #pragma unroll
    for (int j = 0; j < 9; j++) { acc0[j] = 0.f; acc1[j] = 0.f; }

    // score-phase mapping: 4 queries x 4 keys per thread
    const int sq0 = (tid >> 4) << 2;   // 0..60
    const int sk0 = (tid & 15) << 2;   // 0..60

    for (int kt = 0; kt < NKT; kt++) {
        const int k0 = kt * BKV;
        __syncthreads();   // prev-iter PV done before overwriting K/V/Ss

        // load K,V tile
        for (int i = tid; i < BKV * HD; i += 256) {
            int kk = i / HD, d = i - kk * HD;
            int s = k0 + kk;
            float kv = 0.f, vv = 0.f;
            if (s < S_LEN) {
                long off = (rowbase + s) * (long)QKV_N + d;
                kv = kp[off];
                vv = vp[off];
            }
            Ks[kk * HDP + d] = kv;
            Vs[kk * HDP + d] = vv;
        }
        __syncthreads();

        // scores: 4x4 register block, loop over hd
        float sc[4][4];
        #pragma unroll
        for (int i = 0; i < 4; i++)
            #pragma unroll
            for (int j = 0; j < 4; j++) sc[i][j] = 0.f;
        #pragma unroll 8
        for (int d = 0; d < HD; d++) {
            float qa[4], ka[4];
            #pragma unroll
            for (int i = 0; i < 4; i++) qa[i] = Qs[(sq0 + i) * HDP + d];
            #pragma unroll
            for (int j = 0; j < 4; j++) ka[j] = Ks[(sk0 + j) * HDP + d];
            #pragma unroll
            for (int i = 0; i < 4; i++)
                #pragma unroll
                for (int j = 0; j < 4; j++)
                    sc[i][j] += qa[i] * ka[j];
        }
        #pragma unroll
        for (int i = 0; i < 4; i++)
            #pragma unroll
            for (int j = 0; j < 4; j++) {
                bool valid = (k0 + sk0 + j) < S_LEN;
                Ss[(sq0 + i) * SSP + sk0 + j] = valid ? sc[i][j] * SCALE_F : -1e30f;
            }
        __syncthreads();

        // online softmax bookkeeping: one thread per query row
        if (tid < BQ) {
            const int q = tid;
            float m_old = m_s[q];
            float mx = m_old;
            #pragma unroll 8
            for (int j = 0; j < BKV; j++) mx = fmaxf(mx, Ss[q * SSP + j]);
            float r = __expf(m_old - mx);
            float lsum = 0.f;
            #pragma unroll 8
            for (int j = 0; j < BKV; j++) {
                float p = __expf(Ss[q * SSP + j] - mx);
                Ss[q * SSP + j] = p;
                lsum += p;
            }
            m_s[q] = mx;
            l_s[q] = l_s[q] * r + lsum;
            r_s[q] = r;
        }
        __syncthreads();

        // PV accumulate
        const float r0 = r_s[2 * tqp], r1 = r_s[2 * tqp + 1];
        #pragma unroll
        for (int j = 0; j < 9; j++) { acc0[j] *= r0; acc1[j] *= r1; }
        #pragma unroll 4
        for (int j = 0; j < BKV; j++) {
            float p0 = Ss[(2 * tqp) * SSP + j];
            float p1 = Ss[(2 * tqp + 1) * SSP + j];
            #pragma unroll
            for (int dd = 0; dd < 9; dd++) {
                float v = Vs[j * HDP + d0 + dd];
                acc0[dd] += p0 * v;
                acc1[dd] += p1 * v;
            }
        }
    }

    // write output (divide by l)
    {
        int s = q0 + 2 * tqp;
        if (s < S_LEN) {
            float inv = 1.f / l_s[2 * tqp];
            long o = (rowbase + s) * (long)EMB + h * HD + d0;
            #pragma unroll
            for (int dd = 0; dd < 9; dd++) out[o + dd] = acc0[dd] * inv;
        }
        s = q0 + 2 * tqp + 1;
        if (s < S_LEN) {
            float inv = 1.f / l_s[2 * tqp + 1];
            long o = (rowbase + s) * (long)EMB + h * HD + d0;
            #pragma unroll
            for (int dd = 0; dd < 9; dd++) out[o + dd] = acc1[dd] * inv;
        }
    }
}

// ---------------- launch ----------------
extern "C" void kernel_launch(void* const* d_in, const int* in_sizes, int n_in,
                              void* d_out, int out_size)
{
    const float* x      = (const float*)d_in[0];
    const float* w_qkv  = (const float*)d_in[1];
    const float* b_qkv  = (const float*)d_in[2];
    const float* w_out  = (const float*)d_in[3];
    const float* b_out  = (const float*)d_in[4];
    float* out = (float*)d_out;

    void* p_qkv = nullptr;
    void* p_att = nullptr;
    cudaGetSymbolAddress(&p_qkv, g_qkv);
    cudaGetSymbolAddress(&p_att, g_att);
    float* qkv = (float*)p_qkv;
    float* att = (float*)p_att;

    cudaFuncSetAttribute(attn_kernel,
                         cudaFuncAttributeMaxDynamicSharedMemorySize,
                         ATTN_SMEM_BYTES);

    // 1) fused QKV projection: [23328,1152] @ [1152,3456] + bias
    {
        dim3 grid(QKV_N / BN, (ROWS + BM - 1) / BM);
        sgemm_bias<<<grid, 256>>>(x, w_qkv, b_qkv, qkv, ROWS, QKV_N, EMB);
    }
    // 2) attention per (b,h)
    {
        dim3 grid(NKT, BATCH * NH);
        attn_kernel<<<grid, 256, ATTN_SMEM_BYTES>>>(qkv, att);
    }
    // 3) output projection: [23328,1152] @ [1152,1152] + bias
    {
        dim3 grid(EMB / BN, (ROWS + BM - 1) / BM);
        sgemm_bias<<<grid, 256>>>(att, w_out, b_out, out, ROWS, EMB, EMB);
    }
}

// round 3
// speedup vs baseline: 1.4285x; 1.4285x over previous
#include <cuda_runtime.h>
#include <cuda_bf16.h>
#include <cstdint>

// ---------------- problem constants ----------------
#define BATCH   32
#define S_LEN   729
#define EMB     1152
#define NH      16
#define HD      72
#define QKV_N   (3 * EMB)          // 3456
#define ROWS    (BATCH * S_LEN)    // 23328
#define SCALE_F 0.11785113019775792f  // 72^-0.5

// ---------------- scratch (no cudaMalloc allowed) ----------------
__device__ float g_qkv[(size_t)ROWS * QKV_N];   // ~322 MB
__device__ float g_att[(size_t)ROWS * EMB];     // ~107 MB

// =====================================================================
// mma.sync helpers (family-portable PTX; compiles for compute_103)
// =====================================================================
__device__ __forceinline__ uint32_t smem_u32(const void* p) {
    uint32_t a;
    asm("{ .reg .u64 t; cvta.to.shared.u64 t, %1; cvt.u32.u64 %0, t; }"
        : "=r"(a) : "l"(p));
    return a;
}

__device__ __forceinline__ void ldsm_x4(uint32_t& r0, uint32_t& r1,
                                        uint32_t& r2, uint32_t& r3, uint32_t addr) {
    asm volatile("ldmatrix.sync.aligned.m8n8.x4.shared.b16 {%0,%1,%2,%3}, [%4];"
                 : "=r"(r0), "=r"(r1), "=r"(r2), "=r"(r3) : "r"(addr));
}

__device__ __forceinline__ void mma16816(float* c, const uint32_t* a, const uint32_t* b) {
    asm volatile(
        "mma.sync.aligned.m16n8k16.row.col.f32.bf16.bf16.f32 "
        "{%0,%1,%2,%3}, {%4,%5,%6,%7}, {%8,%9}, {%0,%1,%2,%3};"
        : "+f"(c[0]), "+f"(c[1]), "+f"(c[2]), "+f"(c[3])
        : "r"(a[0]), "r"(a[1]), "r"(a[2]), "r"(a[3]), "r"(b[0]), "r"(b[1]));
}

__device__ __forceinline__ unsigned long long pack4bf(float a, float b, float c, float d) {
    __nv_bfloat162 p0 = __floats2bfloat162_rn(a, b);
    __nv_bfloat162 p1 = __floats2bfloat162_rn(c, d);
    unsigned int u0 = *reinterpret_cast<unsigned int*>(&p0);
    unsigned int u1 = *reinterpret_cast<unsigned int*>(&p1);
    return ((unsigned long long)u1 << 32) | u0;
}
#define STS64(addr, v) \
    asm volatile("st.shared.b64 [%0], %1;" :: "r"(addr), "l"(v) : "memory")

// =====================================================================
// tensor-core GEMM, bf16 3-split emulation of fp32
// C[M,N] = A[M,K] @ B[K,N] + bias[N];  N % 128 == 0, K % 64 == 0.
// =====================================================================
#define GK   64                 // K per staged chunk
#define LDA  72                 // padded smem stride in halves (144 B rows)
#define TILE_HALVES (128 * LDA) // 9216 halves = 18432 B per tile
#define OFS_AH 0
#define OFS_AL (TILE_HALVES * 2)
#define OFS_BH (TILE_HALVES * 4)
#define OFS_BL (TILE_HALVES * 6)
#define GEMM_DYN (TILE_HALVES * 8)   // 73728 B

__global__ __launch_bounds__(256) void gemm_mma(
    const float* __restrict__ A, const float* __restrict__ B,
    const float* __restrict__ bias, float* __restrict__ C,
    int M, int N, int K)
{
    extern __shared__ __nv_bfloat16 sm_bf[];
    const uint32_t sbase = smem_u32(sm_bf);

    const int tid  = threadIdx.x;
    const int wid  = tid >> 5;
    const int lane = tid & 31;
    const int wm   = wid >> 1;          // 0..3 (m block of 32)
    const int wn   = wid & 1;           // 0..1 (n block of 64)
    const int m0   = blockIdx.y * 128;
    const int n0   = blockIdx.x * 128;

    float acc[2][8][4];
    #pragma unroll
    for (int i = 0; i < 2; i++)
        #pragma unroll
        for (int j = 0; j < 8; j++)
            #pragma unroll
            for (int t = 0; t < 4; t++) acc[i][j][t] = 0.f;

    const int nchunk = K / GK;
    for (int c = 0; c < nchunk; c++) {
        const int k0g = c * GK;
        __syncthreads();   // compute of prev chunk done before overwrite

        // ---- stage A: 128 rows x 64 k, split hi/lo ----
        #pragma unroll
        for (int i = 0; i < 8; i++) {
            int f  = tid + i * 256;
            int r  = f >> 4;
            int c4 = (f & 15) << 2;
            float4 v = make_float4(0.f, 0.f, 0.f, 0.f);
            if (m0 + r < M)
                v = *reinterpret_cast<const float4*>(A + (size_t)(m0 + r) * K + k0g + c4);
            float h0 = __bfloat162float(__float2bfloat16(v.x));
            float h1 = __bfloat162float(__float2bfloat16(v.y));
            float h2 = __bfloat162float(__float2bfloat16(v.z));
            float h3 = __bfloat162float(__float2bfloat16(v.w));
            uint32_t off = (uint32_t)(r * LDA + c4) * 2;
            STS64(sbase + OFS_AH + off, pack4bf(h0, h1, h2, h3));
            STS64(sbase + OFS_AL + off, pack4bf(v.x - h0, v.y - h1, v.z - h2, v.w - h3));
        }
        // ---- stage B transposed: BT[n][k], split hi/lo ----
        #pragma unroll
        for (int i = 0; i < 8; i++) {
            int g  = tid + i * 256;
            int n  = g & 127;
            int kb = g >> 7;            // 0..15 -> k = 4*kb
            const float* bp = B + (size_t)(k0g + 4 * kb) * N + n0 + n;
            float v0 = bp[0];
            float v1 = bp[(size_t)N];
            float v2 = bp[(size_t)2 * N];
            float v3 = bp[(size_t)3 * N];
            float h0 = __bfloat162float(__float2bfloat16(v0));
            float h1 = __bfloat162float(__float2bfloat16(v1));
            float h2 = __bfloat162float(__float2bfloat16(v2));
            float h3 = __bfloat162float(__float2bfloat16(v3));
            uint32_t off = (uint32_t)(n * LDA + 4 * kb) * 2;
            STS64(sbase + OFS_BH + off, pack4bf(h0, h1, h2, h3));
            STS64(sbase + OFS_BL + off, pack4bf(v0 - h0, v1 - h1, v2 - h2, v3 - h3));
        }
        __syncthreads();

        // ---- compute: 4 k-steps of 16 ----
        #pragma unroll
        for (int kk = 0; kk < 4; kk++) {
            const int k0 = kk * 16;
            uint32_t ah[2][4], al[2][4];
            #pragma unroll
            for (int mt = 0; mt < 2; mt++) {
                int row = wm * 32 + mt * 16 + (lane & 15);
                int col = k0 + ((lane >> 4) << 3);
                uint32_t off = (uint32_t)(row * LDA + col) * 2;
                ldsm_x4(ah[mt][0], ah[mt][1], ah[mt][2], ah[mt][3], sbase + OFS_AH + off);
                ldsm_x4(al[mt][0], al[mt][1], al[mt][2], al[mt][3], sbase + OFS_AL + off);
            }
            uint32_t bh[8][2], bl[8][2];
            #pragma unroll
            for (int np = 0; np < 4; np++) {
                int row = wn * 64 + np * 16 + (lane & 7) + ((lane >> 4) << 3);
                int col = k0 + (((lane >> 3) & 1) << 3);
                uint32_t off = (uint32_t)(row * LDA + col) * 2;
                ldsm_x4(bh[2*np][0], bh[2*np][1], bh[2*np+1][0], bh[2*np+1][1],
                        sbase + OFS_BH + off);
                ldsm_x4(bl[2*np][0], bl[2*np][1], bl[2*np+1][0], bl[2*np+1][1],
                        sbase + OFS_BL + off);
            }
            #pragma unroll
            for (int mt = 0; mt < 2; mt++)
                #pragma unroll
                for (int nt = 0; nt < 8; nt++) {
                    mma16816(acc[mt][nt], ah[mt], bh[nt]);
                    mma16816(acc[mt][nt], ah[mt], bl[nt]);
                    mma16816(acc[mt][nt], al[mt], bh[nt]);
                }
        }
    }

    // ---- epilogue: bias + store ----
    #pragma unroll
    for (int mt = 0; mt < 2; mt++) {
        #pragma unroll
        for (int nt = 0; nt < 8; nt++) {
            int r0 = m0 + wm * 32 + mt * 16 + (lane >> 2);
            int cc = n0 + wn * 64 + nt * 8 + ((lane & 3) << 1);
            float2 bv = *reinterpret_cast<const float2*>(bias + cc);
            if (r0 < M) {
                float2 o = make_float2(acc[mt][nt][0] + bv.x, acc[mt][nt][1] + bv.y);
                *reinterpret_cast<float2*>(C + (size_t)r0 * N + cc) = o;
            }
            int r1 = r0 + 8;
            if (r1 < M) {
                float2 o = make_float2(acc[mt][nt][2] + bv.x, acc[mt][nt][3] + bv.y);
                *reinterpret_cast<float2*>(C + (size_t)r1 * N + cc) = o;
            }
        }
    }
}

// =====================================================================
// flash-style attention (fp32, unchanged from round 1)
// =====================================================================
#define BQ   64
#define BKV  64
#define NKT  12
#define HDP  73
#define SSP  (BKV + 1)
#define ATTN_SMEM_FLOATS (3 * BQ * HDP + BQ * SSP + 3 * BQ)
#define ATTN_SMEM_BYTES  (ATTN_SMEM_FLOATS * 4)

__global__ __launch_bounds__(256) void attn_kernel(
    const float* __restrict__ qkv, float* __restrict__ out)
{
    extern __shared__ float sm[];
    float* Qs  = sm;
    float* Ks  = Qs + BQ * HDP;
    float* Vs  = Ks + BKV * HDP;
    float* Ss  = Vs + BKV * HDP;
    float* m_s = Ss + BQ * SSP;
    float* l_s = m_s + BQ;
    float* r_s = l_s + BQ;

    const int tid = threadIdx.x;
    const int qt  = blockIdx.x;
    const int bh  = blockIdx.y;
    const int b   = bh >> 4;
    const int h   = bh & 15;
    const long rowbase = (long)b * S_LEN;
    const int  q0 = qt * BQ;

    const float* qp = qkv + h * HD;
    const float* kp = qkv + EMB + h * HD;
    const float* vp = qkv + 2 * EMB + h * HD;

    for (int i = tid; i < BQ * HD; i += 256) {
        int q = i / HD, d = i - q * HD;
        int s = q0 + q;
        Qs[q * HDP + d] = (s < S_LEN) ? qp[(rowbase + s) * (long)QKV_N + d] : 0.f;
    }
    if (tid < BQ) { m_s[tid] = -1e30f; l_s[tid] = 0.f; }

    const int tqp = tid >> 3;
    const int tdg = tid & 7;
    const int d0  = tdg * 9;
    float acc0[9], acc1[9];
    #pragma unroll
    for (int j = 0; j < 9; j++) { acc0[j] = 0.f; acc1[j] = 0.f; }

    const int sq0 = (tid >> 4) << 2;
    const int sk0 = (tid & 15) << 2;

    for (int kt = 0; kt < NKT; kt++) {
        const int k0 = kt * BKV;
        __syncthreads();

        for (int i = tid; i < BKV * HD; i += 256) {
            int kk = i / HD, d = i - kk * HD;
            int s = k0 + kk;
            float kv = 0.f, vv = 0.f;
            if (s < S_LEN) {
                long off = (rowbase + s) * (long)QKV_N + d;
                kv = kp[off];
                vv = vp[off];
            }
            Ks[kk * HDP + d] = kv;
            Vs[kk * HDP + d] = vv;
        }
        __syncthreads();

        float sc[4][4];
        #pragma unroll
        for (int i = 0; i < 4; i++)
            #pragma unroll
            for (int j = 0; j < 4; j++) sc[i][j] = 0.f;
        #pragma unroll 8
        for (int d = 0; d < HD; d++) {
            float qa[4], ka[4];
            #pragma unroll
            for (int i = 0; i < 4; i++) qa[i] = Qs[(sq0 + i) * HDP + d];
            #pragma unroll
            for (int j = 0; j < 4; j++) ka[j] = Ks[(sk0 + j) * HDP + d];
            #pragma unroll
            for (int i = 0; i < 4; i++)
                #pragma unroll
                for (int j = 0; j < 4; j++)
                    sc[i][j] += qa[i] * ka[j];
        }
        #pragma unroll
        for (int i = 0; i < 4; i++)
            #pragma unroll
            for (int j = 0; j < 4; j++) {
                bool valid = (k0 + sk0 + j) < S_LEN;
                Ss[(sq0 + i) * SSP + sk0 + j] = valid ? sc[i][j] * SCALE_F : -1e30f;
            }
        __syncthreads();

        if (tid < BQ) {
            const int q = tid;
            float m_old = m_s[q];
            float mx = m_old;
            #pragma unroll 8
            for (int j = 0; j < BKV; j++) mx = fmaxf(mx, Ss[q * SSP + j]);
            float r = __expf(m_old - mx);
            float lsum = 0.f;
            #pragma unroll 8
            for (int j = 0; j < BKV; j++) {
                float p = __expf(Ss[q * SSP + j] - mx);
                Ss[q * SSP + j] = p;
                lsum += p;
            }
            m_s[q] = mx;
            l_s[q] = l_s[q] * r + lsum;
            r_s[q] = r;
        }
        __syncthreads();

        const float r0 = r_s[2 * tqp], r1 = r_s[2 * tqp + 1];
        #pragma unroll
        for (int j = 0; j < 9; j++) { acc0[j] *= r0; acc1[j] *= r1; }
        #pragma unroll 4
        for (int j = 0; j < BKV; j++) {
            float p0 = Ss[(2 * tqp) * SSP + j];
            float p1 = Ss[(2 * tqp + 1) * SSP + j];
            #pragma unroll
            for (int dd = 0; dd < 9; dd++) {
                float v = Vs[j * HDP + d0 + dd];
                acc0[dd] += p0 * v;
                acc1[dd] += p1 * v;
            }
        }
    }

    {
        int s = q0 + 2 * tqp;
        if (s < S_LEN) {
            float inv = 1.f / l_s[2 * tqp];
            long o = (rowbase + s) * (long)EMB + h * HD + d0;
            #pragma unroll
            for (int dd = 0; dd < 9; dd++) out[o + dd] = acc0[dd] * inv;
        }
        s = q0 + 2 * tqp + 1;
        if (s < S_LEN) {
            float inv = 1.f / l_s[2 * tqp + 1];
            long o = (rowbase + s) * (long)EMB + h * HD + d0;
            #pragma unroll
            for (int dd = 0; dd < 9; dd++) out[o + dd] = acc1[dd] * inv;
        }
    }
}

// ---------------- launch ----------------
extern "C" void kernel_launch(void* const* d_in, const int* in_sizes, int n_in,
                              void* d_out, int out_size)
{
    const float* x      = (const float*)d_in[0];
    const float* w_qkv  = (const float*)d_in[1];
    const float* b_qkv  = (const float*)d_in[2];
    const float* w_out  = (const float*)d_in[3];
    const float* b_out  = (const float*)d_in[4];
    float* out = (float*)d_out;

    void* p_qkv = nullptr;
    void* p_att = nullptr;
    cudaGetSymbolAddress(&p_qkv, g_qkv);
    cudaGetSymbolAddress(&p_att, g_att);
    float* qkv = (float*)p_qkv;
    float* att = (float*)p_att;

    cudaFuncSetAttribute(gemm_mma,
                         cudaFuncAttributeMaxDynamicSharedMemorySize, GEMM_DYN);
    cudaFuncSetAttribute(attn_kernel,
                         cudaFuncAttributeMaxDynamicSharedMemorySize, ATTN_SMEM_BYTES);

    // 1) QKV projection: [23328,1152] @ [1152,3456] + bias
    {
        dim3 grid(QKV_N / 128, (ROWS + 127) / 128);
        gemm_mma<<<grid, 256, GEMM_DYN>>>(x, w_qkv, b_qkv, qkv, ROWS, QKV_N, EMB);
    }
    // 2) attention per (b,h)
    {
        dim3 grid(NKT, BATCH * NH);
        attn_kernel<<<grid, 256, ATTN_SMEM_BYTES>>>(qkv, att);
    }
    // 3) output projection: [23328,1152] @ [1152,1152] + bias
    {
        dim3 grid(EMB / 128, (ROWS + 127) / 128);
        gemm_mma<<<grid, 256, GEMM_DYN>>>(att, w_out, b_out, out, ROWS, EMB, EMB);
    }
}

// round 4
// speedup vs baseline: 2.2985x; 1.6090x over previous
#include <cuda_runtime.h>
#include <cuda_bf16.h>
#include <cstdint>

// ---------------- problem constants ----------------
#define BATCH   32
#define S_LEN   729
#define EMB     1152
#define NH      16
#define HD      72
#define QKV_N   (3 * EMB)          // 3456
#define ROWS    (BATCH * S_LEN)    // 23328
#define SCALE_F 0.11785113019775792f  // 72^-0.5
#define SCL2E   (0.11785113019775792f * 1.4426950408889634f)  // scale * log2(e)

// ---------------- scratch (no cudaMalloc allowed) ----------------
__device__ float g_qkv[(size_t)ROWS * QKV_N];   // ~322 MB
__device__ float g_att[(size_t)ROWS * EMB];     // ~107 MB

// =====================================================================
// helpers
// =====================================================================
__device__ __forceinline__ uint32_t smem_u32(const void* p) {
    uint32_t a;
    asm("{ .reg .u64 t; cvta.to.shared.u64 t, %1; cvt.u32.u64 %0, t; }"
        : "=r"(a) : "l"(p));
    return a;
}
__device__ __forceinline__ void ldsm_x4(uint32_t& r0, uint32_t& r1,
                                        uint32_t& r2, uint32_t& r3, uint32_t addr) {
    asm volatile("ldmatrix.sync.aligned.m8n8.x4.shared.b16 {%0,%1,%2,%3}, [%4];"
                 : "=r"(r0), "=r"(r1), "=r"(r2), "=r"(r3) : "r"(addr));
}
__device__ __forceinline__ void ldsm_x4_t(uint32_t& r0, uint32_t& r1,
                                          uint32_t& r2, uint32_t& r3, uint32_t addr) {
    asm volatile("ldmatrix.sync.aligned.m8n8.x4.trans.shared.b16 {%0,%1,%2,%3}, [%4];"
                 : "=r"(r0), "=r"(r1), "=r"(r2), "=r"(r3) : "r"(addr));
}
__device__ __forceinline__ void mma16816(float* c, const uint32_t* a, const uint32_t* b) {
    asm volatile(
        "mma.sync.aligned.m16n8k16.row.col.f32.bf16.bf16.f32 "
        "{%0,%1,%2,%3}, {%4,%5,%6,%7}, {%8,%9}, {%0,%1,%2,%3};"
        : "+f"(c[0]), "+f"(c[1]), "+f"(c[2]), "+f"(c[3])
        : "r"(a[0]), "r"(a[1]), "r"(a[2]), "r"(a[3]), "r"(b[0]), "r"(b[1]));
}
__device__ __forceinline__ unsigned long long pack4bf(float a, float b, float c, float d) {
    __nv_bfloat162 p0 = __floats2bfloat162_rn(a, b);
    __nv_bfloat162 p1 = __floats2bfloat162_rn(c, d);
    unsigned int u0 = *reinterpret_cast<unsigned int*>(&p0);
    unsigned int u1 = *reinterpret_cast<unsigned int*>(&p1);
    return ((unsigned long long)u1 << 32) | u0;
}
__device__ __forceinline__ uint32_t packbf2(float x, float y) {
    __nv_bfloat162 t = __floats2bfloat162_rn(x, y);
    return *reinterpret_cast<uint32_t*>(&t);
}
#define STS64(addr, v) \
    asm volatile("st.shared.b64 [%0], %1;" :: "r"(addr), "l"(v) : "memory")

// FFMA-only 2^t (no MUFU). ~1e-7 accuracy, t clamped at -126.
__device__ __forceinline__ float exp2_fast(float t) {
    t = fmaxf(t, -126.0f);
    float fi = floorf(t);
    float f = t - fi;
    float p = 0.00133335581f;
    p = fmaf(p, f, 0.00961812910f);
    p = fmaf(p, f, 0.0555041087f);
    p = fmaf(p, f, 0.240226507f);
    p = fmaf(p, f, 0.693147180f);
    p = fmaf(p, f, 1.0f);
    return __int_as_float(__float_as_int(p) + ((int)fi << 23));
}

// =====================================================================
// tensor-core GEMM, bf16 3-split, register-prefetch pipeline
// C[M,N] = A[M,K] @ B[K,N] + bias[N];  N % 128 == 0, K % 64 == 0.
// =====================================================================
#define GK   64
#define LDA  72                 // smem stride in halves (144 B rows)
#define TILE_HALVES (128 * LDA)
#define OFS_AH 0
#define OFS_AL (TILE_HALVES * 2)
#define OFS_BH (TILE_HALVES * 4)
#define OFS_BL (TILE_HALVES * 6)
#define GEMM_DYN (TILE_HALVES * 8)   // 73728 B

__global__ __launch_bounds__(256) void gemm_mma(
    const float* __restrict__ A, const float* __restrict__ B,
    const float* __restrict__ bias, float* __restrict__ C,
    int M, int N, int K)
{
    extern __shared__ __nv_bfloat16 sm_bf[];
    const uint32_t sbase = smem_u32(sm_bf);

    const int tid  = threadIdx.x;
    const int wid  = tid >> 5;
    const int lane = tid & 31;
    const int wm   = wid >> 1;
    const int wn   = wid & 1;
    const int m0   = blockIdx.y * 128;
    const int n0   = blockIdx.x * 128;

    float acc[2][8][4];
    #pragma unroll
    for (int i = 0; i < 2; i++)
        #pragma unroll
        for (int j = 0; j < 8; j++)
            #pragma unroll
            for (int t = 0; t < 4; t++) acc[i][j][t] = 0.f;

    // prefetch registers
    float4 pa[8];
    float  pb[8][4];

    // ---- load chunk 0 into regs ----
    {
        #pragma unroll
        for (int i = 0; i < 8; i++) {
            int f  = tid + i * 256;
            int r  = f >> 4;
            int c4 = (f & 15) << 2;
            pa[i] = make_float4(0.f, 0.f, 0.f, 0.f);
            if (m0 + r < M)
                pa[i] = *reinterpret_cast<const float4*>(A + (size_t)(m0 + r) * K + c4);
        }
        #pragma unroll
        for (int i = 0; i < 8; i++) {
            int g  = tid + i * 256;
            int n  = g & 127;
            int kb = g >> 7;
            const float* bp = B + (size_t)(4 * kb) * N + n0 + n;
            pb[i][0] = bp[0];
            pb[i][1] = bp[(size_t)N];
            pb[i][2] = bp[(size_t)2 * N];
            pb[i][3] = bp[(size_t)3 * N];
        }
    }

    const int nchunk = K / GK;
    for (int c = 0; c < nchunk; c++) {
        __syncthreads();   // consumers of previous chunk done

        // ---- store prefetched regs -> smem (split hi/lo) ----
        #pragma unroll
        for (int i = 0; i < 8; i++) {
            int f  = tid + i * 256;
            int r  = f >> 4;
            int c4 = (f & 15) << 2;
            float4 v = pa[i];
            float h0 = __bfloat162float(__float2bfloat16(v.x));
            float h1 = __bfloat162float(__float2bfloat16(v.y));
            float h2 = __bfloat162float(__float2bfloat16(v.z));
            float h3 = __bfloat162float(__float2bfloat16(v.w));
            uint32_t off = (uint32_t)(r * LDA + c4) * 2;
            STS64(sbase + OFS_AH + off, pack4bf(h0, h1, h2, h3));
            STS64(sbase + OFS_AL + off, pack4bf(v.x - h0, v.y - h1, v.z - h2, v.w - h3));
        }
        #pragma unroll
        for (int i = 0; i < 8; i++) {
            int g  = tid + i * 256;
            int n  = g & 127;
            int kb = g >> 7;
            float v0 = pb[i][0], v1 = pb[i][1], v2 = pb[i][2], v3 = pb[i][3];
            float h0 = __bfloat162float(__float2bfloat16(v0));
            float h1 = __bfloat162float(__float2bfloat16(v1));
            float h2 = __bfloat162float(__float2bfloat16(v2));
            float h3 = __bfloat162float(__float2bfloat16(v3));
            uint32_t off = (uint32_t)(n * LDA + 4 * kb) * 2;
            STS64(sbase + OFS_BH + off, pack4bf(h0, h1, h2, h3));
            STS64(sbase + OFS_BL + off, pack4bf(v0 - h0, v1 - h1, v2 - h2, v3 - h3));
        }
        __syncthreads();

        // ---- issue LDGs for next chunk (latency hides under MMAs) ----
        if (c + 1 < nchunk) {
            const int k0g = (c + 1) * GK;
            #pragma unroll
            for (int i = 0; i < 8; i++) {
                int f  = tid + i * 256;
                int r  = f >> 4;
                int c4 = (f & 15) << 2;
                if (m0 + r < M)
                    pa[i] = *reinterpret_cast<const float4*>(A + (size_t)(m0 + r) * K + k0g + c4);
                else
                    pa[i] = make_float4(0.f, 0.f, 0.f, 0.f);
            }
            #pragma unroll
            for (int i = 0; i < 8; i++) {
                int g  = tid + i * 256;
                int n  = g & 127;
                int kb = g >> 7;
                const float* bp = B + (size_t)(k0g + 4 * kb) * N + n0 + n;
                pb[i][0] = bp[0];
                pb[i][1] = bp[(size_t)N];
                pb[i][2] = bp[(size_t)2 * N];
                pb[i][3] = bp[(size_t)3 * N];
            }
        }

        // ---- compute current chunk ----
        #pragma unroll
        for (int kk = 0; kk < 4; kk++) {
            const int k0 = kk * 16;
            uint32_t ah[2][4], al[2][4];
            #pragma unroll
            for (int mt = 0; mt < 2; mt++) {
                int row = wm * 32 + mt * 16 + (lane & 15);
                int col = k0 + ((lane >> 4) << 3);
                uint32_t off = (uint32_t)(row * LDA + col) * 2;
                ldsm_x4(ah[mt][0], ah[mt][1], ah[mt][2], ah[mt][3], sbase + OFS_AH + off);
                ldsm_x4(al[mt][0], al[mt][1], al[mt][2], al[mt][3], sbase + OFS_AL + off);
            }
            uint32_t bh[8][2], bl[8][2];
            #pragma unroll
            for (int np = 0; np < 4; np++) {
                int row = wn * 64 + np * 16 + (lane & 7) + ((lane >> 4) << 3);
                int col = k0 + (((lane >> 3) & 1) << 3);
                uint32_t off = (uint32_t)(row * LDA + col) * 2;
                ldsm_x4(bh[2*np][0], bh[2*np][1], bh[2*np+1][0], bh[2*np+1][1],
                        sbase + OFS_BH + off);
                ldsm_x4(bl[2*np][0], bl[2*np][1], bl[2*np+1][0], bl[2*np+1][1],
                        sbase + OFS_BL + off);
            }
            #pragma unroll
            for (int mt = 0; mt < 2; mt++)
                #pragma unroll
                for (int nt = 0; nt < 8; nt++) {
                    mma16816(acc[mt][nt], ah[mt], bh[nt]);
                    mma16816(acc[mt][nt], ah[mt], bl[nt]);
                    mma16816(acc[mt][nt], al[mt], bh[nt]);
                }
        }
    }

    // ---- epilogue ----
    #pragma unroll
    for (int mt = 0; mt < 2; mt++) {
        #pragma unroll
        for (int nt = 0; nt < 8; nt++) {
            int r0 = m0 + wm * 32 + mt * 16 + (lane >> 2);
            int cc = n0 + wn * 64 + nt * 8 + ((lane & 3) << 1);
            float2 bv = *reinterpret_cast<const float2*>(bias + cc);
            if (r0 < M) {
                float2 o = make_float2(acc[mt][nt][0] + bv.x, acc[mt][nt][1] + bv.y);
                *reinterpret_cast<float2*>(C + (size_t)r0 * N + cc) = o;
            }
            int r1 = r0 + 8;
            if (r1 < M) {
                float2 o = make_float2(acc[mt][nt][2] + bv.x, acc[mt][nt][3] + bv.y);
                *reinterpret_cast<float2*>(C + (size_t)r1 * N + cc) = o;
            }
        }
    }
}

// =====================================================================
// tensor-core flash attention, bf16 3-split, fragment softmax
// 4 warps, BQ=64 rows (16/warp), kv tiles of 64, hd padded 72->80
// =====================================================================
#define ATS   88                         // smem stride (halves), 176B rows
#define AT_TILE (64 * ATS * 2)           // 11264 B per tile
#define AQH 0
#define AQL (1 * AT_TILE)
#define AKH (2 * AT_TILE)
#define AKL (3 * AT_TILE)
#define AVH (4 * AT_TILE)
#define AVL (5 * AT_TILE)
#define ATTN_DYN (6 * AT_TILE)           // 67584 B
#define NKT 12

__global__ __launch_bounds__(128, 2) void attn_mma(
    const float* __restrict__ qkv, float* __restrict__ out)
{
    extern __shared__ __align__(16) char asmem[];
    const uint32_t sb = smem_u32(asmem);

    const int tid  = threadIdx.x;
    const int wid  = tid >> 5;
    const int lane = tid & 31;
    const int qt   = blockIdx.x;
    const int bh   = blockIdx.y;
    const int b    = bh >> 4;
    const int h    = bh & 15;
    const long rowbase = (long)b * S_LEN;
    const int  q0 = qt * 64;

    const float* qp = qkv + h * HD;
    const float* kp = qkv + EMB + h * HD;
    const float* vp = qkv + 2 * EMB + h * HD;

    // zero-fill pad cols 72..79 of all 6 tiles
    for (int i = tid; i < 64 * 2 * 6; i += 128) {
        int t = i / 128;
        int r = (i & 127) >> 1;
        int g = i & 1;
        STS64(sb + t * AT_TILE + (uint32_t)(r * ATS + 72 + g * 4) * 2, 0ull);
    }
    // stage Q (64 x 72), split hi/lo
    for (int i = tid; i < 64 * 18; i += 128) {
        int r  = i / 18;
        int c4 = (i - r * 18) << 2;
        int s  = q0 + r;
        float4 v = make_float4(0.f, 0.f, 0.f, 0.f);
        if (s < S_LEN)
            v = *reinterpret_cast<const float4*>(qp + (rowbase + s) * (long)QKV_N + c4);
        float h0 = __bfloat162float(__float2bfloat16(v.x));
        float h1 = __bfloat162float(__float2bfloat16(v.y));
        float h2 = __bfloat162float(__float2bfloat16(v.z));
        float h3 = __bfloat162float(__float2bfloat16(v.w));
        uint32_t off = (uint32_t)(r * ATS + c4) * 2;
        STS64(sb + AQH + off, pack4bf(h0, h1, h2, h3));
        STS64(sb + AQL + off, pack4bf(v.x - h0, v.y - h1, v.z - h2, v.w - h3));
    }

    // per-lane state: rows r = 16*wid + (lane>>2)  and  +8
    float m0 = -1e30f, m1 = -1e30f, l0 = 0.f, l1 = 0.f;
    float acc[9][4];
    #pragma unroll
    for (int nt = 0; nt < 9; nt++)
        #pragma unroll
        for (int t = 0; t < 4; t++) acc[nt][t] = 0.f;

    for (int kt = 0; kt < NKT; kt++) {
        const int kv0 = kt * 64;
        __syncthreads();   // prior tile's consumers done

        // stage K and V tiles (64 x 72 each), split hi/lo
        for (int i = tid; i < 64 * 18; i += 128) {
            int r  = i / 18;
            int c4 = (i - r * 18) << 2;
            int s  = kv0 + r;
            uint32_t off = (uint32_t)(r * ATS + c4) * 2;
            float4 v = make_float4(0.f, 0.f, 0.f, 0.f);
            if (s < S_LEN)
                v = *reinterpret_cast<const float4*>(kp + (rowbase + s) * (long)QKV_N + c4);
            float h0 = __bfloat162float(__float2bfloat16(v.x));
            float h1 = __bfloat162float(__float2bfloat16(v.y));
            float h2 = __bfloat162float(__float2bfloat16(v.z));
            float h3 = __bfloat162float(__float2bfloat16(v.w));
            STS64(sb + AKH + off, pack4bf(h0, h1, h2, h3));
            STS64(sb + AKL + off, pack4bf(v.x - h0, v.y - h1, v.z - h2, v.w - h3));
            v = make_float4(0.f, 0.f, 0.f, 0.f);
            if (s < S_LEN)
                v = *reinterpret_cast<const float4*>(vp + (rowbase + s) * (long)QKV_N + c4);
            h0 = __bfloat162float(__float2bfloat16(v.x));
            h1 = __bfloat162float(__float2bfloat16(v.y));
            h2 = __bfloat162float(__float2bfloat16(v.z));
            h3 = __bfloat162float(__float2bfloat16(v.w));
            STS64(sb + AVH + off, pack4bf(h0, h1, h2, h3));
            STS64(sb + AVL + off, pack4bf(v.x - h0, v.y - h1, v.z - h2, v.w - h3));
        }
        __syncthreads();

        // ---- S = Q K^T  (8 n-tiles of 8, 5 k-steps of 16, 3-split) ----
        float s[8][4];
        #pragma unroll
        for (int nt = 0; nt < 8; nt++)
            #pragma unroll
            for (int t = 0; t < 4; t++) s[nt][t] = 0.f;

        #pragma unroll
        for (int kk = 0; kk < 5; kk++) {
            const int k0 = kk * 16;
            uint32_t qh[4], ql[4];
            {
                int row = wid * 16 + (lane & 15);
                int col = k0 + ((lane >> 4) << 3);
                uint32_t off = (uint32_t)(row * ATS + col) * 2;
                ldsm_x4(qh[0], qh[1], qh[2], qh[3], sb + AQH + off);
                ldsm_x4(ql[0], ql[1], ql[2], ql[3], sb + AQL + off);
            }
            #pragma unroll
            for (int np = 0; np < 4; np++) {
                int row = np * 16 + (lane & 7) + ((lane >> 4) << 3);
                int col = k0 + (((lane >> 3) & 1) << 3);
                uint32_t off = (uint32_t)(row * ATS + col) * 2;
                uint32_t kh[4], kl[4];
                ldsm_x4(kh[0], kh[1], kh[2], kh[3], sb + AKH + off);
                ldsm_x4(kl[0], kl[1], kl[2], kl[3], sb + AKL + off);
                mma16816(s[2*np],   qh, &kh[0]);
                mma16816(s[2*np],   qh, &kl[0]);
                mma16816(s[2*np],   ql, &kh[0]);
                mma16816(s[2*np+1], qh, &kh[2]);
                mma16816(s[2*np+1], qh, &kl[2]);
                mma16816(s[2*np+1], ql, &kh[2]);
            }
        }

        // ---- fragment softmax (log2 domain) ----
        float mx0 = -1e30f, mx1 = -1e30f;
        #pragma unroll
        for (int nt = 0; nt < 8; nt++) {
            int cg = kv0 + nt * 8 + ((lane & 3) << 1);
            s[nt][0] = (cg     < S_LEN) ? s[nt][0] * SCL2E : -1e30f;
            s[nt][1] = (cg + 1 < S_LEN) ? s[nt][1] * SCL2E : -1e30f;
            s[nt][2] = (cg     < S_LEN) ? s[nt][2] * SCL2E : -1e30f;
            s[nt][3] = (cg + 1 < S_LEN) ? s[nt][3] * SCL2E : -1e30f;
            mx0 = fmaxf(mx0, fmaxf(s[nt][0], s[nt][1]));
            mx1 = fmaxf(mx1, fmaxf(s[nt][2], s[nt][3]));
        }
        mx0 = fmaxf(mx0, __shfl_xor_sync(0xffffffffu, mx0, 1));
        mx0 = fmaxf(mx0, __shfl_xor_sync(0xffffffffu, mx0, 2));
        mx1 = fmaxf(mx1, __shfl_xor_sync(0xffffffffu, mx1, 1));
        mx1 = fmaxf(mx1, __shfl_xor_sync(0xffffffffu, mx1, 2));
        float mn0 = fmaxf(m0, mx0);
        float mn1 = fmaxf(m1, mx1);
        float r0 = exp2_fast(m0 - mn0);
        float r1 = exp2_fast(m1 - mn1);
        m0 = mn0; m1 = mn1;

        uint32_t aPh[4][4], aPl[4][4];
        float ps0 = 0.f, ps1 = 0.f;
        #pragma unroll
        for (int nt = 0; nt < 8; nt++) {
            float p0 = exp2_fast(s[nt][0] - m0);
            float p1 = exp2_fast(s[nt][1] - m0);
            float p2 = exp2_fast(s[nt][2] - m1);
            float p3 = exp2_fast(s[nt][3] - m1);
            ps0 += p0 + p1;
            ps1 += p2 + p3;
            float h0 = __bfloat162float(__float2bfloat16(p0));
            float h1 = __bfloat162float(__float2bfloat16(p1));
            float h2 = __bfloat162float(__float2bfloat16(p2));
            float h3 = __bfloat162float(__float2bfloat16(p3));
            int kk = nt >> 1, ix = (nt & 1) << 1;
            aPh[kk][ix]     = packbf2(h0, h1);
            aPh[kk][ix + 1] = packbf2(h2, h3);
            aPl[kk][ix]     = packbf2(p0 - h0, p1 - h1);
            aPl[kk][ix + 1] = packbf2(p2 - h2, p3 - h3);
        }
        l0 = l0 * r0 + ps0;
        l1 = l1 * r1 + ps1;
        #pragma unroll
        for (int nt = 0; nt < 9; nt++) {
            acc[nt][0] *= r0; acc[nt][1] *= r0;
            acc[nt][2] *= r1; acc[nt][3] *= r1;
        }

        // ---- O += P V  (A = P frags, B = V^T via ldmatrix.trans) ----
        #pragma unroll
        for (int kk = 0; kk < 4; kk++) {
            #pragma unroll
            for (int np = 0; np < 5; np++) {
                int krow = kk * 16 + (lane & 7) + (((lane >> 3) & 1) << 3);
                int ncol = np * 16 + ((lane >> 4) << 3);
                uint32_t off = (uint32_t)(krow * ATS + ncol) * 2;
                uint32_t vh[4], vl[4];
                ldsm_x4_t(vh[0], vh[1], vh[2], vh[3], sb + AVH + off);
                ldsm_x4_t(vl[0], vl[1], vl[2], vl[3], sb + AVL + off);
                int nt0 = 2 * np, nt1 = 2 * np + 1;
                mma16816(acc[nt0], aPh[kk], &vh[0]);
                mma16816(acc[nt0], aPh[kk], &vl[0]);
                mma16816(acc[nt0], aPl[kk], &vh[0]);
                if (nt1 < 9) {
                    mma16816(acc[nt1], aPh[kk], &vh[2]);
                    mma16816(acc[nt1], aPh[kk], &vl[2]);
                    mma16816(acc[nt1], aPl[kk], &vh[2]);
                }
            }
        }
    }

    // ---- finalize: reduce l across the 4 lanes of each row group ----
    l0 += __shfl_xor_sync(0xffffffffu, l0, 1);
    l0 += __shfl_xor_sync(0xffffffffu, l0, 2);
    l1 += __shfl_xor_sync(0xffffffffu, l1, 1);
    l1 += __shfl_xor_sync(0xffffffffu, l1, 2);
    float inv0 = 1.f / l0;
    float inv1 = 1.f / l1;

    int rg0 = q0 + wid * 16 + (lane >> 2);
    int rg1 = rg0 + 8;
    #pragma unroll
    for (int nt = 0; nt < 9; nt++) {
        int col = h * HD + nt * 8 + ((lane & 3) << 1);
        if (rg0 < S_LEN) {
            float2 o = make_float2(acc[nt][0] * inv0, acc[nt][1] * inv0);
            *reinterpret_cast<float2*>(out + (rowbase + rg0) * (long)EMB + col) = o;
        }
        if (rg1 < S_LEN) {
            float2 o = make_float2(acc[nt][2] * inv1, acc[nt][3] * inv1);
            *reinterpret_cast<float2*>(out + (rowbase + rg1) * (long)EMB + col) = o;
        }
    }
}

// ---------------- launch ----------------
extern "C" void kernel_launch(void* const* d_in, const int* in_sizes, int n_in,
                              void* d_out, int out_size)
{
    const float* x      = (const float*)d_in[0];
    const float* w_qkv  = (const float*)d_in[1];
    const float* b_qkv  = (const float*)d_in[2];
    const float* w_out  = (const float*)d_in[3];
    const float* b_out  = (const float*)d_in[4];
    float* out = (float*)d_out;

    void* p_qkv = nullptr;
    void* p_att = nullptr;
    cudaGetSymbolAddress(&p_qkv, g_qkv);
    cudaGetSymbolAddress(&p_att, g_att);
    float* qkv = (float*)p_qkv;
    float* att = (float*)p_att;

    cudaFuncSetAttribute(gemm_mma,
                         cudaFuncAttributeMaxDynamicSharedMemorySize, GEMM_DYN);
    cudaFuncSetAttribute(attn_mma,
                         cudaFuncAttributeMaxDynamicSharedMemorySize, ATTN_DYN);

    // 1) QKV projection
    {
        dim3 grid(QKV_N / 128, (ROWS + 127) / 128);
        gemm_mma<<<grid, 256, GEMM_DYN>>>(x, w_qkv, b_qkv, qkv, ROWS, QKV_N, EMB);
    }
    // 2) attention
    {
        dim3 grid(NKT, BATCH * NH);
        attn_mma<<<grid, 128, ATTN_DYN>>>(qkv, att);
    }
    // 3) output projection
    {
        dim3 grid(EMB / 128, (ROWS + 127) / 128);
        gemm_mma<<<grid, 256, GEMM_DYN>>>(att, w_out, b_out, out, ROWS, EMB, EMB);
    }
}

// round 5
// speedup vs baseline: 2.7983x; 1.2175x over previous
#include <cuda_runtime.h>
#include <cuda_bf16.h>
#include <cstdint>

// ---------------- problem constants ----------------
#define BATCH   32
#define S_LEN   729
#define EMB     1152
#define NH      16
#define HD      72
#define QKV_N   (3 * EMB)          // 3456
#define ROWS    (BATCH * S_LEN)    // 23328
#define SCL2E   (0.11785113019775792f * 1.4426950408889634f)  // scale * log2(e)

// ---------------- bf16 hi/lo plane scratch (no cudaMalloc allowed) ----
__device__ __nv_bfloat16 g_xh[(size_t)ROWS * EMB];
__device__ __nv_bfloat16 g_xl[(size_t)ROWS * EMB];
__device__ __nv_bfloat16 g_wqh[(size_t)QKV_N * EMB];   // transposed [N][K]
__device__ __nv_bfloat16 g_wql[(size_t)QKV_N * EMB];
__device__ __nv_bfloat16 g_woh[(size_t)EMB * EMB];     // transposed [N][K]
__device__ __nv_bfloat16 g_wol[(size_t)EMB * EMB];
__device__ __nv_bfloat16 g_qh[(size_t)ROWS * QKV_N];   // qkv hi
__device__ __nv_bfloat16 g_ql[(size_t)ROWS * QKV_N];   // qkv lo
__device__ __nv_bfloat16 g_ah[(size_t)ROWS * EMB];     // attn out hi
__device__ __nv_bfloat16 g_al[(size_t)ROWS * EMB];     // attn out lo

// =====================================================================
// helpers
// =====================================================================
__device__ __forceinline__ uint32_t smem_u32(const void* p) {
    uint32_t a;
    asm("{ .reg .u64 t; cvta.to.shared.u64 t, %1; cvt.u32.u64 %0, t; }"
        : "=r"(a) : "l"(p));
    return a;
}
__device__ __forceinline__ void ldsm_x4(uint32_t& r0, uint32_t& r1,
                                        uint32_t& r2, uint32_t& r3, uint32_t addr) {
    asm volatile("ldmatrix.sync.aligned.m8n8.x4.shared.b16 {%0,%1,%2,%3}, [%4];"
                 : "=r"(r0), "=r"(r1), "=r"(r2), "=r"(r3) : "r"(addr));
}
__device__ __forceinline__ void ldsm_x4_t(uint32_t& r0, uint32_t& r1,
                                          uint32_t& r2, uint32_t& r3, uint32_t addr) {
    asm volatile("ldmatrix.sync.aligned.m8n8.x4.trans.shared.b16 {%0,%1,%2,%3}, [%4];"
                 : "=r"(r0), "=r"(r1), "=r"(r2), "=r"(r3) : "r"(addr));
}
__device__ __forceinline__ void mma16816(float* c, const uint32_t* a, const uint32_t* b) {
    asm volatile(
        "mma.sync.aligned.m16n8k16.row.col.f32.bf16.bf16.f32 "
        "{%0,%1,%2,%3}, {%4,%5,%6,%7}, {%8,%9}, {%0,%1,%2,%3};"
        : "+f"(c[0]), "+f"(c[1]), "+f"(c[2]), "+f"(c[3])
        : "r"(a[0]), "r"(a[1]), "r"(a[2]), "r"(a[3]), "r"(b[0]), "r"(b[1]));
}
__device__ __forceinline__ uint32_t packbf2(float x, float y) {
    __nv_bfloat162 t = __floats2bfloat162_rn(x, y);
    return *reinterpret_cast<uint32_t*>(&t);
}
__device__ __forceinline__ unsigned long long pack4bf(float a, float b, float c, float d) {
    uint32_t u0 = packbf2(a, b);
    uint32_t u1 = packbf2(c, d);
    return ((unsigned long long)u1 << 32) | u0;
}
#define STS64(addr, v) \
    asm volatile("st.shared.b64 [%0], %1;" :: "r"(addr), "l"(v) : "memory")

#define CPASYNC(dst, src, sz) \
    asm volatile("cp.async.cg.shared.global [%0], [%1], 16, %2;" \
                 :: "r"(dst), "l"(src), "r"(sz) : "memory")
#define CPCOMMIT() asm volatile("cp.async.commit_group;" ::: "memory")
#define CPWAIT0()  asm volatile("cp.async.wait_group 0;" ::: "memory")
#define CPWAIT1()  asm volatile("cp.async.wait_group 1;" ::: "memory")

// FFMA-only 2^t (no MUFU)
__device__ __forceinline__ float exp2_fast(float t) {
    t = fmaxf(t, -126.0f);
    float fi = floorf(t);
    float f = t - fi;
    float p = 0.00133335581f;
    p = fmaf(p, f, 0.00961812910f);
    p = fmaf(p, f, 0.0555041087f);
    p = fmaf(p, f, 0.240226507f);
    p = fmaf(p, f, 0.693147180f);
    p = fmaf(p, f, 1.0f);
    return __int_as_float(__float_as_int(p) + ((int)fi << 23));
}

// =====================================================================
// conversion kernels
// =====================================================================
// fp32 -> bf16 hi/lo, same layout
__global__ __launch_bounds__(256) void split_rows(
    const float* __restrict__ X, __nv_bfloat16* __restrict__ H,
    __nv_bfloat16* __restrict__ L, size_t n4)
{
    size_t stride = (size_t)gridDim.x * 256;
    for (size_t i = (size_t)blockIdx.x * 256 + threadIdx.x; i < n4; i += stride) {
        float4 v = reinterpret_cast<const float4*>(X)[i];
        float h0 = __bfloat162float(__float2bfloat16(v.x));
        float h1 = __bfloat162float(__float2bfloat16(v.y));
        float h2 = __bfloat162float(__float2bfloat16(v.z));
        float h3 = __bfloat162float(__float2bfloat16(v.w));
        reinterpret_cast<unsigned long long*>(H)[i] = pack4bf(h0, h1, h2, h3);
        reinterpret_cast<unsigned long long*>(L)[i] =
            pack4bf(v.x - h0, v.y - h1, v.z - h2, v.w - h3);
    }
}

// W[K][N] fp32 -> Th/Tl[N][K] bf16 (tiled transpose + split)
__global__ __launch_bounds__(256) void tsplit(
    const float* __restrict__ W, __nv_bfloat16* __restrict__ Th,
    __nv_bfloat16* __restrict__ Tl, int K, int N)
{
    __shared__ float t[32][33];
    const int n0 = blockIdx.x * 32, k0 = blockIdx.y * 32;
    const int tx = threadIdx.x & 31, ty = threadIdx.x >> 5;
    #pragma unroll
    for (int i = 0; i < 4; i++) {
        int kk = ty + i * 8;
        t[kk][tx] = W[(size_t)(k0 + kk) * N + n0 + tx];
    }
    __syncthreads();
    #pragma unroll
    for (int i = 0; i < 4; i++) {
        int nn = ty + i * 8;
        float v = t[tx][nn];
        float h = __bfloat162float(__float2bfloat16(v));
        Th[(size_t)(n0 + nn) * K + k0 + tx] = __float2bfloat16(v);
        Tl[(size_t)(n0 + nn) * K + k0 + tx] = __float2bfloat16(v - h);
    }
}

// =====================================================================
// tensor-core GEMM: pre-split bf16 planes, cp.async 2-stage pipeline
// C = A @ Bt^T + bias;  A[M,K] hi/lo, Bt[N,K] hi/lo. N%128==0, K%64==0.
// Output: fp32 Cf, or hi/lo planes Ch/Cl if Cf == nullptr.
// =====================================================================
#define GK   64
#define ROWB 144                        // smem row stride bytes (72 halves)
#define PLANE_B (128 * ROWB)            // 18432 B
#define OFS_AH 0
#define OFS_AL (1 * PLANE_B)
#define OFS_BH (2 * PLANE_B)
#define OFS_BL (3 * PLANE_B)
#define STAGE_B (4 * PLANE_B)           // 73728
#define GEMM_DYN (2 * STAGE_B)          // 147456

__device__ __forceinline__ void gemm_issue(
    const __nv_bfloat16* __restrict__ Ah, const __nv_bfloat16* __restrict__ Al,
    const __nv_bfloat16* __restrict__ Bth, const __nv_bfloat16* __restrict__ Btl,
    int M, int K, int m0, int n0, int k0, uint32_t stage, int tid)
{
    #pragma unroll
    for (int i = 0; i < 4; i++) {
        int f  = tid + i * 256;
        int r  = f >> 3;
        int sg = f & 7;
        uint32_t doff = (uint32_t)(r * ROWB + sg * 16);
        // A planes (row guard)
        int ar = (m0 + r < M) ? (m0 + r) : (M - 1);
        int sz = (m0 + r < M) ? 16 : 0;
        size_t aoff = (size_t)ar * K + k0 + sg * 8;
        CPASYNC(stage + OFS_AH + doff, Ah + aoff, sz);
        CPASYNC(stage + OFS_AL + doff, Al + aoff, sz);
        // B planes (always valid)
        size_t boff = (size_t)(n0 + r) * K + k0 + sg * 8;
        CPASYNC(stage + OFS_BH + doff, Bth + boff, 16);
        CPASYNC(stage + OFS_BL + doff, Btl + boff, 16);
    }
}

__global__ __launch_bounds__(256) void gemm_bf(
    const __nv_bfloat16* __restrict__ Ah, const __nv_bfloat16* __restrict__ Al,
    const __nv_bfloat16* __restrict__ Bth, const __nv_bfloat16* __restrict__ Btl,
    const float* __restrict__ bias, float* __restrict__ Cf,
    __nv_bfloat16* __restrict__ Ch, __nv_bfloat16* __restrict__ Cl,
    int M, int N, int K)
{
    extern __shared__ __align__(16) char smem[];
    const uint32_t sbase = smem_u32(smem);

    const int tid  = threadIdx.x;
    const int wid  = tid >> 5;
    const int lane = tid & 31;
    const int wm   = wid >> 1;
    const int wn   = wid & 1;
    const int m0   = blockIdx.y * 128;
    const int n0   = blockIdx.x * 128;

    float acc[2][8][4];
    #pragma unroll
    for (int i = 0; i < 2; i++)
        #pragma unroll
        for (int j = 0; j < 8; j++)
            #pragma unroll
            for (int t = 0; t < 4; t++) acc[i][j][t] = 0.f;

    const int nchunk = K / GK;
    gemm_issue(Ah, Al, Bth, Btl, M, K, m0, n0, 0, sbase, tid);
    CPCOMMIT();
    gemm_issue(Ah, Al, Bth, Btl, M, K, m0, n0, GK, sbase + STAGE_B, tid);
    CPCOMMIT();

    for (int c = 0; c < nchunk; c++) {
        const uint32_t st = sbase + (c & 1) * STAGE_B;
        CPWAIT1();
        __syncthreads();

        #pragma unroll
        for (int kk = 0; kk < 4; kk++) {
            const int k0 = kk * 16;
            uint32_t ah[2][4], al[2][4];
            #pragma unroll
            for (int mt = 0; mt < 2; mt++) {
                int row = wm * 32 + mt * 16 + (lane & 15);
                int col = k0 + ((lane >> 4) << 3);
                uint32_t off = (uint32_t)(row * ROWB + col * 2);
                ldsm_x4(ah[mt][0], ah[mt][1], ah[mt][2], ah[mt][3], st + OFS_AH + off);
                ldsm_x4(al[mt][0], al[mt][1], al[mt][2], al[mt][3], st + OFS_AL + off);
            }
            uint32_t bh[8][2], bl[8][2];
            #pragma unroll
            for (int np = 0; np < 4; np++) {
                int row = wn * 64 + np * 16 + (lane & 7) + ((lane >> 4) << 3);
                int col = k0 + (((lane >> 3) & 1) << 3);
                uint32_t off = (uint32_t)(row * ROWB + col * 2);
                ldsm_x4(bh[2*np][0], bh[2*np][1], bh[2*np+1][0], bh[2*np+1][1],
                        st + OFS_BH + off);
                ldsm_x4(bl[2*np][0], bl[2*np][1], bl[2*np+1][0], bl[2*np+1][1],
                        st + OFS_BL + off);
            }
            #pragma unroll
            for (int mt = 0; mt < 2; mt++)
                #pragma unroll
                for (int nt = 0; nt < 8; nt++) {
                    mma16816(acc[mt][nt], ah[mt], bh[nt]);
                    mma16816(acc[mt][nt], ah[mt], bl[nt]);
                    mma16816(acc[mt][nt], al[mt], bh[nt]);
                }
        }
        __syncthreads();
        if (c + 2 < nchunk)
            gemm_issue(Ah, Al, Bth, Btl, M, K, m0, n0, (c + 2) * GK, st, tid);
        CPCOMMIT();
    }

    // ---- epilogue ----
    #pragma unroll
    for (int mt = 0; mt < 2; mt++) {
        #pragma unroll
        for (int nt = 0; nt < 8; nt++) {
            int r0 = m0 + wm * 32 + mt * 16 + (lane >> 2);
            int r1 = r0 + 8;
            int cc = n0 + wn * 64 + nt * 8 + ((lane & 3) << 1);
            float2 bv = *reinterpret_cast<const float2*>(bias + cc);
            float o0 = acc[mt][nt][0] + bv.x;
            float o1 = acc[mt][nt][1] + bv.y;
            float o2 = acc[mt][nt][2] + bv.x;
            float o3 = acc[mt][nt][3] + bv.y;
            if (Cf) {
                if (r0 < M)
                    *reinterpret_cast<float2*>(Cf + (size_t)r0 * N + cc) = make_float2(o0, o1);
                if (r1 < M)
                    *reinterpret_cast<float2*>(Cf + (size_t)r1 * N + cc) = make_float2(o2, o3);
            } else {
                if (r0 < M) {
                    float h0 = __bfloat162float(__float2bfloat16(o0));
                    float h1 = __bfloat162float(__float2bfloat16(o1));
                    *reinterpret_cast<uint32_t*>(Ch + (size_t)r0 * N + cc) = packbf2(h0, h1);
                    *reinterpret_cast<uint32_t*>(Cl + (size_t)r0 * N + cc) =
                        packbf2(o0 - h0, o1 - h1);
                }
                if (r1 < M) {
                    float h2 = __bfloat162float(__float2bfloat16(o2));
                    float h3 = __bfloat162float(__float2bfloat16(o3));
                    *reinterpret_cast<uint32_t*>(Ch + (size_t)r1 * N + cc) = packbf2(h2, h3);
                    *reinterpret_cast<uint32_t*>(Cl + (size_t)r1 * N + cc) =
                        packbf2(o2 - h2, o3 - h3);
                }
            }
        }
    }
}

// =====================================================================
// tensor-core flash attention on pre-split planes
// =====================================================================
#define ATS   88
#define AROWB (ATS * 2)                  // 176 B
#define AT_TILE (64 * AROWB)             // 11264 B
#define AQH 0
#define AQL (1 * AT_TILE)
#define AKH (2 * AT_TILE)
#define AKL (3 * AT_TILE)
#define AVH (4 * AT_TILE)
#define AVL (5 * AT_TILE)
#define ATTN_DYN (6 * AT_TILE)
#define NKT 12

__global__ __launch_bounds__(128, 2) void attn_mma(
    const __nv_bfloat16* __restrict__ qh, const __nv_bfloat16* __restrict__ ql,
    __nv_bfloat16* __restrict__ atth, __nv_bfloat16* __restrict__ attl)
{
    extern __shared__ __align__(16) char asmem[];
    const uint32_t sb = smem_u32(asmem);

    const int tid  = threadIdx.x;
    const int wid  = tid >> 5;
    const int lane = tid & 31;
    const int qt   = blockIdx.x;
    const int bh   = blockIdx.y;
    const int b    = bh >> 4;
    const int h    = bh & 15;
    const long rowbase = (long)b * S_LEN;
    const int  q0 = qt * 64;

    const int qc = h * HD;                // q col in plane
    const int kc = EMB + h * HD;
    const int vc = 2 * EMB + h * HD;

    // zero pads (cols 72..79) for all 6 tiles
    for (int i = tid; i < 64 * 2 * 6; i += 128) {
        int t = i / 128;
        int r = (i & 127) >> 1;
        int g = i & 1;
        STS64(sb + t * AT_TILE + (uint32_t)(r * AROWB + (72 + g * 4) * 2), 0ull);
    }
    // stage Q hi/lo via cp.async (9 x 16B segs per row)
    for (int i = tid; i < 64 * 9; i += 128) {
        int r = i / 9, sg = i - r * 9;
        int s = q0 + r;
        int ar = (s < S_LEN) ? s : (S_LEN - 1);
        int sz = (s < S_LEN) ? 16 : 0;
        size_t goff = (rowbase + ar) * (size_t)QKV_N + qc + sg * 8;
        uint32_t doff = (uint32_t)(r * AROWB + sg * 16);
        CPASYNC(sb + AQH + doff, qh + goff, sz);
        CPASYNC(sb + AQL + doff, ql + goff, sz);
    }
    CPCOMMIT();

    float m0 = -1e30f, m1 = -1e30f, l0 = 0.f, l1 = 0.f;
    float acc[9][4];
    #pragma unroll
    for (int nt = 0; nt < 9; nt++)
        #pragma unroll
        for (int t = 0; t < 4; t++) acc[nt][t] = 0.f;

    for (int kt = 0; kt < NKT; kt++) {
        const int kv0 = kt * 64;
        __syncthreads();   // prior tile consumers done

        for (int i = tid; i < 64 * 9; i += 128) {
            int r = i / 9, sg = i - r * 9;
            int s = kv0 + r;
            int ar = (s < S_LEN) ? s : (S_LEN - 1);
            int sz = (s < S_LEN) ? 16 : 0;
            size_t gk = (rowbase + ar) * (size_t)QKV_N + kc + sg * 8;
            size_t gv = (rowbase + ar) * (size_t)QKV_N + vc + sg * 8;
            uint32_t doff = (uint32_t)(r * AROWB + sg * 16);
            CPASYNC(sb + AKH + doff, qh + gk, sz);
            CPASYNC(sb + AKL + doff, ql + gk, sz);
            CPASYNC(sb + AVH + doff, qh + gv, sz);
            CPASYNC(sb + AVL + doff, ql + gv, sz);
        }
        CPCOMMIT();
        CPWAIT0();
        __syncthreads();

        // ---- S = Q K^T ----
        float s[8][4];
        #pragma unroll
        for (int nt = 0; nt < 8; nt++)
            #pragma unroll
            for (int t = 0; t < 4; t++) s[nt][t] = 0.f;

        #pragma unroll
        for (int kk = 0; kk < 5; kk++) {
            const int k0 = kk * 16;
            uint32_t qfh[4], qfl[4];
            {
                int row = wid * 16 + (lane & 15);
                int col = k0 + ((lane >> 4) << 3);
                uint32_t off = (uint32_t)(row * AROWB + col * 2);
                ldsm_x4(qfh[0], qfh[1], qfh[2], qfh[3], sb + AQH + off);
                ldsm_x4(qfl[0], qfl[1], qfl[2], qfl[3], sb + AQL + off);
            }
            #pragma unroll
            for (int np = 0; np < 4; np++) {
                int row = np * 16 + (lane & 7) + ((lane >> 4) << 3);
                int col = k0 + (((lane >> 3) & 1) << 3);
                uint32_t off = (uint32_t)(row * AROWB + col * 2);
                uint32_t kh[4], kl[4];
                ldsm_x4(kh[0], kh[1], kh[2], kh[3], sb + AKH + off);
                ldsm_x4(kl[0], kl[1], kl[2], kl[3], sb + AKL + off);
                mma16816(s[2*np],   qfh, &kh[0]);
                mma16816(s[2*np],   qfh, &kl[0]);
                mma16816(s[2*np],   qfl, &kh[0]);
                mma16816(s[2*np+1], qfh, &kh[2]);
                mma16816(s[2*np+1], qfh, &kl[2]);
                mma16816(s[2*np+1], qfl, &kh[2]);
            }
        }

        // ---- fragment softmax (log2 domain) ----
        float mx0 = -1e30f, mx1 = -1e30f;
        #pragma unroll
        for (int nt = 0; nt < 8; nt++) {
            int cg = kv0 + nt * 8 + ((lane & 3) << 1);
            s[nt][0] = (cg     < S_LEN) ? s[nt][0] * SCL2E : -1e30f;
            s[nt][1] = (cg + 1 < S_LEN) ? s[nt][1] * SCL2E : -1e30f;
            s[nt][2] = (cg     < S_LEN) ? s[nt][2] * SCL2E : -1e30f;
            s[nt][3] = (cg + 1 < S_LEN) ? s[nt][3] * SCL2E : -1e30f;
            mx0 = fmaxf(mx0, fmaxf(s[nt][0], s[nt][1]));
            mx1 = fmaxf(mx1, fmaxf(s[nt][2], s[nt][3]));
        }
        mx0 = fmaxf(mx0, __shfl_xor_sync(0xffffffffu, mx0, 1));
        mx0 = fmaxf(mx0, __shfl_xor_sync(0xffffffffu, mx0, 2));
        mx1 = fmaxf(mx1, __shfl_xor_sync(0xffffffffu, mx1, 1));
        mx1 = fmaxf(mx1, __shfl_xor_sync(0xffffffffu, mx1, 2));
        float mn0 = fmaxf(m0, mx0);
        float mn1 = fmaxf(m1, mx1);
        float r0 = exp2_fast(m0 - mn0);
        float r1 = exp2_fast(m1 - mn1);
        m0 = mn0; m1 = mn1;

        uint32_t aPh[4][4], aPl[4][4];
        float ps0 = 0.f, ps1 = 0.f;
        #pragma unroll
        for (int nt = 0; nt < 8; nt++) {
            float p0 = exp2_fast(s[nt][0] - m0);
            float p1 = exp2_fast(s[nt][1] - m0);
            float p2 = exp2_fast(s[nt][2] - m1);
            float p3 = exp2_fast(s[nt][3] - m1);
            ps0 += p0 + p1;
            ps1 += p2 + p3;
            float h0 = __bfloat162float(__float2bfloat16(p0));
            float h1 = __bfloat162float(__float2bfloat16(p1));
            float h2 = __bfloat162float(__float2bfloat16(p2));
            float h3 = __bfloat162float(__float2bfloat16(p3));
            int kk = nt >> 1, ix = (nt & 1) << 1;
            aPh[kk][ix]     = packbf2(h0, h1);
            aPh[kk][ix + 1] = packbf2(h2, h3);
            aPl[kk][ix]     = packbf2(p0 - h0, p1 - h1);
            aPl[kk][ix + 1] = packbf2(p2 - h2, p3 - h3);
        }
        l0 = l0 * r0 + ps0;
        l1 = l1 * r1 + ps1;
        #pragma unroll
        for (int nt = 0; nt < 9; nt++) {
            acc[nt][0] *= r0; acc[nt][1] *= r0;
            acc[nt][2] *= r1; acc[nt][3] *= r1;
        }

        // ---- O += P V ----
        #pragma unroll
        for (int kk = 0; kk < 4; kk++) {
            #pragma unroll
            for (int np = 0; np < 5; np++) {
                int krow = kk * 16 + (lane & 7) + (((lane >> 3) & 1) << 3);
                int ncol = np * 16 + ((lane >> 4) << 3);
                uint32_t off = (uint32_t)(krow * AROWB + ncol * 2);
                uint32_t vh[4], vl[4];
                ldsm_x4_t(vh[0], vh[1], vh[2], vh[3], sb + AVH + off);
                ldsm_x4_t(vl[0], vl[1], vl[2], vl[3], sb + AVL + off);
                int nt0 = 2 * np, nt1 = 2 * np + 1;
                mma16816(acc[nt0], aPh[kk], &vh[0]);
                mma16816(acc[nt0], aPh[kk], &vl[0]);
                mma16816(acc[nt0], aPl[kk], &vh[0]);
                if (nt1 < 9) {
                    mma16816(acc[nt1], aPh[kk], &vh[2]);
                    mma16816(acc[nt1], aPh[kk], &vl[2]);
                    mma16816(acc[nt1], aPl[kk], &vh[2]);
                }
            }
        }
    }

    // ---- finalize ----
    l0 += __shfl_xor_sync(0xffffffffu, l0, 1);
    l0 += __shfl_xor_sync(0xffffffffu, l0, 2);
    l1 += __shfl_xor_sync(0xffffffffu, l1, 1);
    l1 += __shfl_xor_sync(0xffffffffu, l1, 2);
    float inv0 = 1.f / l0;
    float inv1 = 1.f / l1;

    int rg0 = q0 + wid * 16 + (lane >> 2);
    int rg1 = rg0 + 8;
    #pragma unroll
    for (int nt = 0; nt < 9; nt++) {
        int col = h * HD + nt * 8 + ((lane & 3) << 1);
        if (rg0 < S_LEN) {
            float o0 = acc[nt][0] * inv0;
            float o1 = acc[nt][1] * inv0;
            float h0 = __bfloat162float(__float2bfloat16(o0));
            float h1 = __bfloat162float(__float2bfloat16(o1));
            size_t off = (rowbase + rg0) * (size_t)EMB + col;
            *reinterpret_cast<uint32_t*>(atth + off) = packbf2(h0, h1);
            *reinterpret_cast<uint32_t*>(attl + off) = packbf2(o0 - h0, o1 - h1);
        }
        if (rg1 < S_LEN) {
            float o2 = acc[nt][2] * inv1;
            float o3 = acc[nt][3] * inv1;
            float h2 = __bfloat162float(__float2bfloat16(o2));
            float h3 = __bfloat162float(__float2bfloat16(o3));
            size_t off = (rowbase + rg1) * (size_t)EMB + col;
            *reinterpret_cast<uint32_t*>(atth + off) = packbf2(h2, h3);
            *reinterpret_cast<uint32_t*>(attl + off) = packbf2(o2 - h2, o3 - h3);
        }
    }
}

// ---------------- launch ----------------
extern "C" void kernel_launch(void* const* d_in, const int* in_sizes, int n_in,
                              void* d_out, int out_size)
{
    const float* x      = (const float*)d_in[0];
    const float* w_qkv  = (const float*)d_in[1];
    const float* b_qkv  = (const float*)d_in[2];
    const float* w_out  = (const float*)d_in[3];
    const float* b_out  = (const float*)d_in[4];
    float* out = (float*)d_out;

    void *xh, *xl, *wqh, *wql, *woh, *wol, *qh, *ql, *ah, *al;
    cudaGetSymbolAddress(&xh,  g_xh);   cudaGetSymbolAddress(&xl,  g_xl);
    cudaGetSymbolAddress(&wqh, g_wqh);  cudaGetSymbolAddress(&wql, g_wql);
    cudaGetSymbolAddress(&woh, g_woh);  cudaGetSymbolAddress(&wol, g_wol);
    cudaGetSymbolAddress(&qh,  g_qh);   cudaGetSymbolAddress(&ql,  g_ql);
    cudaGetSymbolAddress(&ah,  g_ah);   cudaGetSymbolAddress(&al,  g_al);

    cudaFuncSetAttribute(gemm_bf,
                         cudaFuncAttributeMaxDynamicSharedMemorySize, GEMM_DYN);
    cudaFuncSetAttribute(attn_mma,
                         cudaFuncAttributeMaxDynamicSharedMemorySize, ATTN_DYN);

    // 0) conversions
    split_rows<<<4096, 256>>>(x, (__nv_bfloat16*)xh, (__nv_bfloat16*)xl,
                              (size_t)ROWS * EMB / 4);
    tsplit<<<dim3(QKV_N / 32, EMB / 32), 256>>>(w_qkv, (__nv_bfloat16*)wqh,
                                                (__nv_bfloat16*)wql, EMB, QKV_N);
    tsplit<<<dim3(EMB / 32, EMB / 32), 256>>>(w_out, (__nv_bfloat16*)woh,
                                              (__nv_bfloat16*)wol, EMB, EMB);

    // 1) QKV projection -> bf16 hi/lo planes
    {
        dim3 grid(QKV_N / 128, (ROWS + 127) / 128);
        gemm_bf<<<grid, 256, GEMM_DYN>>>(
            (const __nv_bfloat16*)xh, (const __nv_bfloat16*)xl,
            (const __nv_bfloat16*)wqh, (const __nv_bfloat16*)wql,
            b_qkv, nullptr, (__nv_bfloat16*)qh, (__nv_bfloat16*)ql,
            ROWS, QKV_N, EMB);
    }
    // 2) attention -> bf16 hi/lo planes
    {
        dim3 grid(NKT, BATCH * NH);
        attn_mma<<<grid, 128, ATTN_DYN>>>(
            (const __nv_bfloat16*)qh, (const __nv_bfloat16*)ql,
            (__nv_bfloat16*)ah, (__nv_bfloat16*)al);
    }
    // 3) output projection -> fp32 out
    {
        dim3 grid(EMB / 128, (ROWS + 127) / 128);
        gemm_bf<<<grid, 256, GEMM_DYN>>>(
            (const __nv_bfloat16*)ah, (const __nv_bfloat16*)al,
            (const __nv_bfloat16*)woh, (const __nv_bfloat16*)wol,
            b_out, out, nullptr, nullptr,
            ROWS, EMB, EMB);
    }
}

// round 6
// speedup vs baseline: 2.9693x; 1.0611x over previous
#include <cuda_runtime.h>
#include <cuda_bf16.h>
#include <cstdint>

// ---------------- problem constants ----------------
#define BATCH   32
#define S_LEN   729
#define EMB     1152
#define NH      16
#define HD      72
#define QKV_N   (3 * EMB)          // 3456
#define ROWS    (BATCH * S_LEN)    // 23328
#define SCL2E   (0.11785113019775792f * 1.4426950408889634f)  // scale * log2(e)

// ---------------- bf16 hi/lo plane scratch (no cudaMalloc allowed) ----
__device__ __nv_bfloat16 g_xh[(size_t)ROWS * EMB];
__device__ __nv_bfloat16 g_xl[(size_t)ROWS * EMB];
__device__ __nv_bfloat16 g_wqh[(size_t)QKV_N * EMB];   // transposed [N][K]
__device__ __nv_bfloat16 g_wql[(size_t)QKV_N * EMB];
__device__ __nv_bfloat16 g_woh[(size_t)EMB * EMB];     // transposed [N][K]
__device__ __nv_bfloat16 g_wol[(size_t)EMB * EMB];
__device__ __nv_bfloat16 g_qh[(size_t)ROWS * QKV_N];   // qkv hi
__device__ __nv_bfloat16 g_ql[(size_t)ROWS * QKV_N];   // qkv lo
__device__ __nv_bfloat16 g_ah[(size_t)ROWS * EMB];     // attn out hi
__device__ __nv_bfloat16 g_al[(size_t)ROWS * EMB];     // attn out lo

// =====================================================================
// helpers
// =====================================================================
__device__ __forceinline__ uint32_t smem_u32(const void* p) {
    uint32_t a;
    asm("{ .reg .u64 t; cvta.to.shared.u64 t, %1; cvt.u32.u64 %0, t; }"
        : "=r"(a) : "l"(p));
    return a;
}
__device__ __forceinline__ void ldsm_x4(uint32_t& r0, uint32_t& r1,
                                        uint32_t& r2, uint32_t& r3, uint32_t addr) {
    asm volatile("ldmatrix.sync.aligned.m8n8.x4.shared.b16 {%0,%1,%2,%3}, [%4];"
                 : "=r"(r0), "=r"(r1), "=r"(r2), "=r"(r3) : "r"(addr));
}
__device__ __forceinline__ void ldsm_x4_t(uint32_t& r0, uint32_t& r1,
                                          uint32_t& r2, uint32_t& r3, uint32_t addr) {
    asm volatile("ldmatrix.sync.aligned.m8n8.x4.trans.shared.b16 {%0,%1,%2,%3}, [%4];"
                 : "=r"(r0), "=r"(r1), "=r"(r2), "=r"(r3) : "r"(addr));
}
__device__ __forceinline__ void mma16816(float* c, const uint32_t* a, const uint32_t* b) {
    asm volatile(
        "mma.sync.aligned.m16n8k16.row.col.f32.bf16.bf16.f32 "
        "{%0,%1,%2,%3}, {%4,%5,%6,%7}, {%8,%9}, {%0,%1,%2,%3};"
        : "+f"(c[0]), "+f"(c[1]), "+f"(c[2]), "+f"(c[3])
        : "r"(a[0]), "r"(a[1]), "r"(a[2]), "r"(a[3]), "r"(b[0]), "r"(b[1]));
}
__device__ __forceinline__ uint32_t packbf2(float x, float y) {
    __nv_bfloat162 t = __floats2bfloat162_rn(x, y);
    return *reinterpret_cast<uint32_t*>(&t);
}
__device__ __forceinline__ unsigned long long pack4bf(float a, float b, float c, float d) {
    uint32_t u0 = packbf2(a, b);
    uint32_t u1 = packbf2(c, d);
    return ((unsigned long long)u1 << 32) | u0;
}
#define STS64(addr, v) \
    asm volatile("st.shared.b64 [%0], %1;" :: "r"(addr), "l"(v) : "memory")

#define CPASYNC(dst, src, sz) \
    asm volatile("cp.async.cg.shared.global [%0], [%1], 16, %2;" \
                 :: "r"(dst), "l"(src), "r"(sz) : "memory")
#define CPCOMMIT() asm volatile("cp.async.commit_group;" ::: "memory")
#define CPWAIT0()  asm volatile("cp.async.wait_group 0;" ::: "memory")
#define CPWAIT1()  asm volatile("cp.async.wait_group 1;" ::: "memory")

// FFMA-only 2^t (no MUFU)
__device__ __forceinline__ float exp2_fast(float t) {
    t = fmaxf(t, -126.0f);
    float fi = floorf(t);
    float f = t - fi;
    float p = 0.00133335581f;
    p = fmaf(p, f, 0.00961812910f);
    p = fmaf(p, f, 0.0555041087f);
    p = fmaf(p, f, 0.240226507f);
    p = fmaf(p, f, 0.693147180f);
    p = fmaf(p, f, 1.0f);
    return __int_as_float(__float_as_int(p) + ((int)fi << 23));
}

// =====================================================================
// conversion kernels
// =====================================================================
__global__ __launch_bounds__(256) void split_rows(
    const float* __restrict__ X, __nv_bfloat16* __restrict__ H,
    __nv_bfloat16* __restrict__ L, size_t n4)
{
    size_t stride = (size_t)gridDim.x * 256;
    for (size_t i = (size_t)blockIdx.x * 256 + threadIdx.x; i < n4; i += stride) {
        float4 v = reinterpret_cast<const float4*>(X)[i];
        float h0 = __bfloat162float(__float2bfloat16(v.x));
        float h1 = __bfloat162float(__float2bfloat16(v.y));
        float h2 = __bfloat162float(__float2bfloat16(v.z));
        float h3 = __bfloat162float(__float2bfloat16(v.w));
        reinterpret_cast<unsigned long long*>(H)[i] = pack4bf(h0, h1, h2, h3);
        reinterpret_cast<unsigned long long*>(L)[i] =
            pack4bf(v.x - h0, v.y - h1, v.z - h2, v.w - h3);
    }
}

__global__ __launch_bounds__(256) void tsplit(
    const float* __restrict__ W, __nv_bfloat16* __restrict__ Th,
    __nv_bfloat16* __restrict__ Tl, int K, int N)
{
    __shared__ float t[32][33];
    const int n0 = blockIdx.x * 32, k0 = blockIdx.y * 32;
    const int tx = threadIdx.x & 31, ty = threadIdx.x >> 5;
    #pragma unroll
    for (int i = 0; i < 4; i++) {
        int kk = ty + i * 8;
        t[kk][tx] = W[(size_t)(k0 + kk) * N + n0 + tx];
    }
    __syncthreads();
    #pragma unroll
    for (int i = 0; i < 4; i++) {
        int nn = ty + i * 8;
        float v = t[tx][nn];
        float h = __bfloat162float(__float2bfloat16(v));
        Th[(size_t)(n0 + nn) * K + k0 + tx] = __float2bfloat16(v);
        Tl[(size_t)(n0 + nn) * K + k0 + tx] = __float2bfloat16(v - h);
    }
}

// =====================================================================
// tensor-core GEMM: pre-split planes, cp.async 2-stage, 2 CTAs/SM
// C = A @ Bt^T + bias;  A[M,K] hi/lo, Bt[N,K] hi/lo. N%128==0, K%32==0.
// =====================================================================
#define GK    32
#define ROWB  80                        // smem row stride bytes (32 halves + pad)
#define PLANE_B (128 * ROWB)            // 10240 B
#define OFS_AH 0
#define OFS_AL (1 * PLANE_B)
#define OFS_BH (2 * PLANE_B)
#define OFS_BL (3 * PLANE_B)
#define STAGE_B (4 * PLANE_B)           // 40960
#define GEMM_DYN (2 * STAGE_B)          // 81920 -> 2 CTAs/SM

__device__ __forceinline__ void gemm_issue(
    const __nv_bfloat16* __restrict__ Ah, const __nv_bfloat16* __restrict__ Al,
    const __nv_bfloat16* __restrict__ Bth, const __nv_bfloat16* __restrict__ Btl,
    int M, int K, int m0, int n0, int k0, uint32_t stage, int tid)
{
    #pragma unroll
    for (int i = 0; i < 2; i++) {
        int f  = tid + i * 256;         // 0..511
        int r  = f >> 2;                // row 0..127
        int sg = f & 3;                 // 16B segment 0..3
        uint32_t doff = (uint32_t)(r * ROWB + sg * 16);
        int ar = (m0 + r < M) ? (m0 + r) : (M - 1);
        int sz = (m0 + r < M) ? 16 : 0;
        size_t aoff = (size_t)ar * K + k0 + sg * 8;
        CPASYNC(stage + OFS_AH + doff, Ah + aoff, sz);
        CPASYNC(stage + OFS_AL + doff, Al + aoff, sz);
        size_t boff = (size_t)(n0 + r) * K + k0 + sg * 8;
        CPASYNC(stage + OFS_BH + doff, Bth + boff, 16);
        CPASYNC(stage + OFS_BL + doff, Btl + boff, 16);
    }
}

__global__ __launch_bounds__(256, 2) void gemm_bf(
    const __nv_bfloat16* __restrict__ Ah, const __nv_bfloat16* __restrict__ Al,
    const __nv_bfloat16* __restrict__ Bth, const __nv_bfloat16* __restrict__ Btl,
    const float* __restrict__ bias, float* __restrict__ Cf,
    __nv_bfloat16* __restrict__ Ch, __nv_bfloat16* __restrict__ Cl,
    int M, int N, int K)
{
    extern __shared__ __align__(16) char smem[];
    const uint32_t sbase = smem_u32(smem);

    const int tid  = threadIdx.x;
    const int wid  = tid >> 5;
    const int lane = tid & 31;
    const int wm   = wid >> 1;
    const int wn   = wid & 1;
    const int m0   = blockIdx.y * 128;
    const int n0   = blockIdx.x * 128;

    float acc[2][8][4];
    #pragma unroll
    for (int i = 0; i < 2; i++)
        #pragma unroll
        for (int j = 0; j < 8; j++)
            #pragma unroll
            for (int t = 0; t < 4; t++) acc[i][j][t] = 0.f;

    const int nchunk = K / GK;
    gemm_issue(Ah, Al, Bth, Btl, M, K, m0, n0, 0, sbase, tid);
    CPCOMMIT();
    gemm_issue(Ah, Al, Bth, Btl, M, K, m0, n0, GK, sbase + STAGE_B, tid);
    CPCOMMIT();

    for (int c = 0; c < nchunk; c++) {
        const uint32_t st = sbase + (c & 1) * STAGE_B;
        CPWAIT1();
        __syncthreads();

        #pragma unroll
        for (int kk = 0; kk < 2; kk++) {
            const int k0 = kk * 16;
            uint32_t ah[2][4], al[2][4];
            #pragma unroll
            for (int mt = 0; mt < 2; mt++) {
                int row = wm * 32 + mt * 16 + (lane & 15);
                int col = k0 + ((lane >> 4) << 3);
                uint32_t off = (uint32_t)(row * ROWB + col * 2);
                ldsm_x4(ah[mt][0], ah[mt][1], ah[mt][2], ah[mt][3], st + OFS_AH + off);
                ldsm_x4(al[mt][0], al[mt][1], al[mt][2], al[mt][3], st + OFS_AL + off);
            }
            #pragma unroll
            for (int np = 0; np < 4; np++) {
                int row = wn * 64 + np * 16 + (lane & 7) + ((lane >> 4) << 3);
                int col = k0 + (((lane >> 3) & 1) << 3);
                uint32_t off = (uint32_t)(row * ROWB + col * 2);
                uint32_t bh[4], bl[4];
                ldsm_x4(bh[0], bh[1], bh[2], bh[3], st + OFS_BH + off);
                ldsm_x4(bl[0], bl[1], bl[2], bl[3], st + OFS_BL + off);
                #pragma unroll
                for (int mt = 0; mt < 2; mt++) {
                    mma16816(acc[mt][2*np],   ah[mt], &bh[0]);
                    mma16816(acc[mt][2*np],   ah[mt], &bl[0]);
                    mma16816(acc[mt][2*np],   al[mt], &bh[0]);
                    mma16816(acc[mt][2*np+1], ah[mt], &bh[2]);
                    mma16816(acc[mt][2*np+1], ah[mt], &bl[2]);
                    mma16816(acc[mt][2*np+1], al[mt], &bh[2]);
                }
            }
        }
        __syncthreads();
        if (c + 2 < nchunk)
            gemm_issue(Ah, Al, Bth, Btl, M, K, m0, n0, (c + 2) * GK, st, tid);
        CPCOMMIT();
    }

    // ---- epilogue ----
    #pragma unroll
    for (int mt = 0; mt < 2; mt++) {
        #pragma unroll
        for (int nt = 0; nt < 8; nt++) {
            int r0 = m0 + wm * 32 + mt * 16 + (lane >> 2);
            int r1 = r0 + 8;
            int cc = n0 + wn * 64 + nt * 8 + ((lane & 3) << 1);
            float2 bv = *reinterpret_cast<const float2*>(bias + cc);
            float o0 = acc[mt][nt][0] + bv.x;
            float o1 = acc[mt][nt][1] + bv.y;
            float o2 = acc[mt][nt][2] + bv.x;
            float o3 = acc[mt][nt][3] + bv.y;
            if (Cf) {
                if (r0 < M)
                    *reinterpret_cast<float2*>(Cf + (size_t)r0 * N + cc) = make_float2(o0, o1);
                if (r1 < M)
                    *reinterpret_cast<float2*>(Cf + (size_t)r1 * N + cc) = make_float2(o2, o3);
            } else {
                if (r0 < M) {
                    float h0 = __bfloat162float(__float2bfloat16(o0));
                    float h1 = __bfloat162float(__float2bfloat16(o1));
                    *reinterpret_cast<uint32_t*>(Ch + (size_t)r0 * N + cc) = packbf2(h0, h1);
                    *reinterpret_cast<uint32_t*>(Cl + (size_t)r0 * N + cc) =
                        packbf2(o0 - h0, o1 - h1);
                }
                if (r1 < M) {
                    float h2 = __bfloat162float(__float2bfloat16(o2));
                    float h3 = __bfloat162float(__float2bfloat16(o3));
                    *reinterpret_cast<uint32_t*>(Ch + (size_t)r1 * N + cc) = packbf2(h2, h3);
                    *reinterpret_cast<uint32_t*>(Cl + (size_t)r1 * N + cc) =
                        packbf2(o2 - h2, o3 - h3);
                }
            }
        }
    }
}

// =====================================================================
// tensor-core flash attention on pre-split planes (unchanged)
// =====================================================================
#define ATS   88
#define AROWB (ATS * 2)
#define AT_TILE (64 * AROWB)
#define AQH 0
#define AQL (1 * AT_TILE)
#define AKH (2 * AT_TILE)
#define AKL (3 * AT_TILE)
#define AVH (4 * AT_TILE)
#define AVL (5 * AT_TILE)
#define ATTN_DYN (6 * AT_TILE)
#define NKT 12

__global__ __launch_bounds__(128, 2) void attn_mma(
    const __nv_bfloat16* __restrict__ qh, const __nv_bfloat16* __restrict__ ql,
    __nv_bfloat16* __restrict__ atth, __nv_bfloat16* __restrict__ attl)
{
    extern __shared__ __align__(16) char asmem[];
    const uint32_t sb = smem_u32(asmem);

    const int tid  = threadIdx.x;
    const int wid  = tid >> 5;
    const int lane = tid & 31;
    const int qt   = blockIdx.x;
    const int bh   = blockIdx.y;
    const int b    = bh >> 4;
    const int h    = bh & 15;
    const long rowbase = (long)b * S_LEN;
    const int  q0 = qt * 64;

    const int qc = h * HD;
    const int kc = EMB + h * HD;
    const int vc = 2 * EMB + h * HD;

    for (int i = tid; i < 64 * 2 * 6; i += 128) {
        int t = i / 128;
        int r = (i & 127) >> 1;
        int g = i & 1;
        STS64(sb + t * AT_TILE + (uint32_t)(r * AROWB + (72 + g * 4) * 2), 0ull);
    }
    for (int i = tid; i < 64 * 9; i += 128) {
        int r = i / 9, sg = i - r * 9;
        int s = q0 + r;
        int ar = (s < S_LEN) ? s : (S_LEN - 1);
        int sz = (s < S_LEN) ? 16 : 0;
        size_t goff = (rowbase + ar) * (size_t)QKV_N + qc + sg * 8;
        uint32_t doff = (uint32_t)(r * AROWB + sg * 16);
        CPASYNC(sb + AQH + doff, qh + goff, sz);
        CPASYNC(sb + AQL + doff, ql + goff, sz);
    }
    CPCOMMIT();

    float m0 = -1e30f, m1 = -1e30f, l0 = 0.f, l1 = 0.f;
    float acc[9][4];
    #pragma unroll
    for (int nt = 0; nt < 9; nt++)
        #pragma unroll
        for (int t = 0; t < 4; t++) acc[nt][t] = 0.f;

    for (int kt = 0; kt < NKT; kt++) {
        const int kv0 = kt * 64;
        __syncthreads();

        for (int i = tid; i < 64 * 9; i += 128) {
            int r = i / 9, sg = i - r * 9;
            int s = kv0 + r;
            int ar = (s < S_LEN) ? s : (S_LEN - 1);
            int sz = (s < S_LEN) ? 16 : 0;
            size_t gk = (rowbase + ar) * (size_t)QKV_N + kc + sg * 8;
            size_t gv = (rowbase + ar) * (size_t)QKV_N + vc + sg * 8;
            uint32_t doff = (uint32_t)(r * AROWB + sg * 16);
            CPASYNC(sb + AKH + doff, qh + gk, sz);
            CPASYNC(sb + AKL + doff, ql + gk, sz);
            CPASYNC(sb + AVH + doff, qh + gv, sz);
            CPASYNC(sb + AVL + doff, ql + gv, sz);
        }
        CPCOMMIT();
        CPWAIT0();
        __syncthreads();

        float s[8][4];
        #pragma unroll
        for (int nt = 0; nt < 8; nt++)
            #pragma unroll
            for (int t = 0; t < 4; t++) s[nt][t] = 0.f;

        #pragma unroll
        for (int kk = 0; kk < 5; kk++) {
            const int k0 = kk * 16;
            uint32_t qfh[4], qfl[4];
            {
                int row = wid * 16 + (lane & 15);
                int col = k0 + ((lane >> 4) << 3);
                uint32_t off = (uint32_t)(row * AROWB + col * 2);
                ldsm_x4(qfh[0], qfh[1], qfh[2], qfh[3], sb + AQH + off);
                ldsm_x4(qfl[0], qfl[1], qfl[2], qfl[3], sb + AQL + off);
            }
            #pragma unroll
            for (int np = 0; np < 4; np++) {
                int row = np * 16 + (lane & 7) + ((lane >> 4) << 3);
                int col = k0 + (((lane >> 3) & 1) << 3);
                uint32_t off = (uint32_t)(row * AROWB + col * 2);
                uint32_t kh[4], kl[4];
                ldsm_x4(kh[0], kh[1], kh[2], kh[3], sb + AKH + off);
                ldsm_x4(kl[0], kl[1], kl[2], kl[3], sb + AKL + off);
                mma16816(s[2*np],   qfh, &kh[0]);
                mma16816(s[2*np],   qfh, &kl[0]);
                mma16816(s[2*np],   qfl, &kh[0]);
                mma16816(s[2*np+1], qfh, &kh[2]);
                mma16816(s[2*np+1], qfh, &kl[2]);
                mma16816(s[2*np+1], qfl, &kh[2]);
            }
        }

        float mx0 = -1e30f, mx1 = -1e30f;
        #pragma unroll
        for (int nt = 0; nt < 8; nt++) {
            int cg = kv0 + nt * 8 + ((lane & 3) << 1);
            s[nt][0] = (cg     < S_LEN) ? s[nt][0] * SCL2E : -1e30f;
            s[nt][1] = (cg + 1 < S_LEN) ? s[nt][1] * SCL2E : -1e30f;
            s[nt][2] = (cg     < S_LEN) ? s[nt][2] * SCL2E : -1e30f;
            s[nt][3] = (cg + 1 < S_LEN) ? s[nt][3] * SCL2E : -1e30f;
            mx0 = fmaxf(mx0, fmaxf(s[nt][0], s[nt][1]));
            mx1 = fmaxf(mx1, fmaxf(s[nt][2], s[nt][3]));
        }
        mx0 = fmaxf(mx0, __shfl_xor_sync(0xffffffffu, mx0, 1));
        mx0 = fmaxf(mx0, __shfl_xor_sync(0xffffffffu, mx0, 2));
        mx1 = fmaxf(mx1, __shfl_xor_sync(0xffffffffu, mx1, 1));
        mx1 = fmaxf(mx1, __shfl_xor_sync(0xffffffffu, mx1, 2));
        float mn0 = fmaxf(m0, mx0);
        float mn1 = fmaxf(m1, mx1);
        float r0 = exp2_fast(m0 - mn0);
        float r1 = exp2_fast(m1 - mn1);
        m0 = mn0; m1 = mn1;

        uint32_t aPh[4][4], aPl[4][4];
        float ps0 = 0.f, ps1 = 0.f;
        #pragma unroll
        for (int nt = 0; nt < 8; nt++) {
            float p0 = exp2_fast(s[nt][0] - m0);
            float p1 = exp2_fast(s[nt][1] - m0);
            float p2 = exp2_fast(s[nt][2] - m1);
            float p3 = exp2_fast(s[nt][3] - m1);
            ps0 += p0 + p1;
            ps1 += p2 + p3;
            float h0 = __bfloat162float(__float2bfloat16(p0));
            float h1 = __bfloat162float(__float2bfloat16(p1));
            float h2 = __bfloat162float(__float2bfloat16(p2));
            float h3 = __bfloat162float(__float2bfloat16(p3));
            int kk = nt >> 1, ix = (nt & 1) << 1;
            aPh[kk][ix]     = packbf2(h0, h1);
            aPh[kk][ix + 1] = packbf2(h2, h3);
            aPl[kk][ix]     = packbf2(p0 - h0, p1 - h1);
            aPl[kk][ix + 1] = packbf2(p2 - h2, p3 - h3);
        }
        l0 = l0 * r0 + ps0;
        l1 = l1 * r1 + ps1;
        #pragma unroll
        for (int nt = 0; nt < 9; nt++) {
            acc[nt][0] *= r0; acc[nt][1] *= r0;
            acc[nt][2] *= r1; acc[nt][3] *= r1;
        }

        #pragma unroll
        for (int kk = 0; kk < 4; kk++) {
            #pragma unroll
            for (int np = 0; np < 5; np++) {
                int krow = kk * 16 + (lane & 7) + (((lane >> 3) & 1) << 3);
                int ncol = np * 16 + ((lane >> 4) << 3);
                uint32_t off = (uint32_t)(krow * AROWB + ncol * 2);
                uint32_t vh[4], vl[4];
                ldsm_x4_t(vh[0], vh[1], vh[2], vh[3], sb + AVH + off);
                ldsm_x4_t(vl[0], vl[1], vl[2], vl[3], sb + AVL + off);
                int nt0 = 2 * np, nt1 = 2 * np + 1;
                mma16816(acc[nt0], aPh[kk], &vh[0]);
                mma16816(acc[nt0], aPh[kk], &vl[0]);
                mma16816(acc[nt0], aPl[kk], &vh[0]);
                if (nt1 < 9) {
                    mma16816(acc[nt1], aPh[kk], &vh[2]);
                    mma16816(acc[nt1], aPh[kk], &vl[2]);
                    mma16816(acc[nt1], aPl[kk], &vh[2]);
                }
            }
        }
    }

    l0 += __shfl_xor_sync(0xffffffffu, l0, 1);
    l0 += __shfl_xor_sync(0xffffffffu, l0, 2);
    l1 += __shfl_xor_sync(0xffffffffu, l1, 1);
    l1 += __shfl_xor_sync(0xffffffffu, l1, 2);
    float inv0 = 1.f / l0;
    float inv1 = 1.f / l1;

    int rg0 = q0 + wid * 16 + (lane >> 2);
    int rg1 = rg0 + 8;
    #pragma unroll
    for (int nt = 0; nt < 9; nt++) {
        int col = h * HD + nt * 8 + ((lane & 3) << 1);
        if (rg0 < S_LEN) {
            float o0 = acc[nt][0] * inv0;
            float o1 = acc[nt][1] * inv0;
            float h0 = __bfloat162float(__float2bfloat16(o0));
            float h1 = __bfloat162float(__float2bfloat16(o1));
            size_t off = (rowbase + rg0) * (size_t)EMB + col;
            *reinterpret_cast<uint32_t*>(atth + off) = packbf2(h0, h1);
            *reinterpret_cast<uint32_t*>(attl + off) = packbf2(o0 - h0, o1 - h1);
        }
        if (rg1 < S_LEN) {
            float o2 = acc[nt][2] * inv1;
            float o3 = acc[nt][3] * inv1;
            float h2 = __bfloat162float(__float2bfloat16(o2));
            float h3 = __bfloat162float(__float2bfloat16(o3));
            size_t off = (rowbase + rg1) * (size_t)EMB + col;
            *reinterpret_cast<uint32_t*>(atth + off) = packbf2(h2, h3);
            *reinterpret_cast<uint32_t*>(attl + off) = packbf2(o2 - h2, o3 - h3);
        }
    }
}

// ---------------- launch ----------------
extern "C" void kernel_launch(void* const* d_in, const int* in_sizes, int n_in,
                              void* d_out, int out_size)
{
    const float* x      = (const float*)d_in[0];
    const float* w_qkv  = (const float*)d_in[1];
    const float* b_qkv  = (const float*)d_in[2];
    const float* w_out  = (const float*)d_in[3];
    const float* b_out  = (const float*)d_in[4];
    float* out = (float*)d_out;

    void *xh, *xl, *wqh, *wql, *woh, *wol, *qh, *ql, *ah, *al;
    cudaGetSymbolAddress(&xh,  g_xh);   cudaGetSymbolAddress(&xl,  g_xl);
    cudaGetSymbolAddress(&wqh, g_wqh);  cudaGetSymbolAddress(&wql, g_wql);
    cudaGetSymbolAddress(&woh, g_woh);  cudaGetSymbolAddress(&wol, g_wol);
    cudaGetSymbolAddress(&qh,  g_qh);   cudaGetSymbolAddress(&ql,  g_ql);
    cudaGetSymbolAddress(&ah,  g_ah);   cudaGetSymbolAddress(&al,  g_al);

    cudaFuncSetAttribute(gemm_bf,
                         cudaFuncAttributeMaxDynamicSharedMemorySize, GEMM_DYN);
    cudaFuncSetAttribute(attn_mma,
                         cudaFuncAttributeMaxDynamicSharedMemorySize, ATTN_DYN);

    // 0) conversions
    split_rows<<<4096, 256>>>(x, (__nv_bfloat16*)xh, (__nv_bfloat16*)xl,
                              (size_t)ROWS * EMB / 4);
    tsplit<<<dim3(QKV_N / 32, EMB / 32), 256>>>(w_qkv, (__nv_bfloat16*)wqh,
                                                (__nv_bfloat16*)wql, EMB, QKV_N);
    tsplit<<<dim3(EMB / 32, EMB / 32), 256>>>(w_out, (__nv_bfloat16*)woh,
                                              (__nv_bfloat16*)wol, EMB, EMB);

    // 1) QKV projection -> bf16 hi/lo planes
    {
        dim3 grid(QKV_N / 128, (ROWS + 127) / 128);
        gemm_bf<<<grid, 256, GEMM_DYN>>>(
            (const __nv_bfloat16*)xh, (const __nv_bfloat16*)xl,
            (const __nv_bfloat16*)wqh, (const __nv_bfloat16*)wql,
            b_qkv, nullptr, (__nv_bfloat16*)qh, (__nv_bfloat16*)ql,
            ROWS, QKV_N, EMB);
    }
    // 2) attention -> bf16 hi/lo planes
    {
        dim3 grid(NKT, BATCH * NH);
        attn_mma<<<grid, 128, ATTN_DYN>>>(
            (const __nv_bfloat16*)qh, (const __nv_bfloat16*)ql,
            (__nv_bfloat16*)ah, (__nv_bfloat16*)al);
    }
    // 3) output projection -> fp32 out
    {
        dim3 grid(EMB / 128, (ROWS + 127) / 128);
        gemm_bf<<<grid, 256, GEMM_DYN>>>(
            (const __nv_bfloat16*)ah, (const __nv_bfloat16*)al,
            (const __nv_bfloat16*)woh, (const __nv_bfloat16*)wol,
            b_out, out, nullptr, nullptr,
            ROWS, EMB, EMB);
    }
}

// round 7
// speedup vs baseline: 3.7242x; 1.2542x over previous
#include <cuda_runtime.h>
#include <cuda_bf16.h>
#include <cstdint>

// ---------------- problem constants ----------------
#define BATCH   32
#define S_LEN   729
#define EMB     1152
#define NH      16
#define HD      72
#define QKV_N   (3 * EMB)          // 3456
#define ROWS    (BATCH * S_LEN)    // 23328
#define SCL2E   (0.11785113019775792f * 1.4426950408889634f)  // scale * log2(e)

// ---------------- scratch (no cudaMalloc allowed) ----------------
__device__ float         g_xr [(size_t)ROWS * EMB];     // x, tf32-rounded
__device__ float         g_wqt[(size_t)QKV_N * EMB];    // w_qkv^T [N][K], tf32-rounded
__device__ float         g_wot[(size_t)EMB * EMB];      // w_out^T [N][K], tf32-rounded
__device__ __nv_bfloat16 g_qh [(size_t)ROWS * QKV_N];   // qkv hi (for attention)
__device__ __nv_bfloat16 g_ql [(size_t)ROWS * QKV_N];   // qkv lo
__device__ float         g_att[(size_t)ROWS * EMB];     // attn out, tf32-rounded

// =====================================================================
// helpers
// =====================================================================
__device__ __forceinline__ uint32_t smem_u32(const void* p) {
    uint32_t a;
    asm("{ .reg .u64 t; cvta.to.shared.u64 t, %1; cvt.u32.u64 %0, t; }"
        : "=r"(a) : "l"(p));
    return a;
}
__device__ __forceinline__ void ldsm_x4(uint32_t& r0, uint32_t& r1,
                                        uint32_t& r2, uint32_t& r3, uint32_t addr) {
    asm volatile("ldmatrix.sync.aligned.m8n8.x4.shared.b16 {%0,%1,%2,%3}, [%4];"
                 : "=r"(r0), "=r"(r1), "=r"(r2), "=r"(r3) : "r"(addr));
}
__device__ __forceinline__ void ldsm_x4_t(uint32_t& r0, uint32_t& r1,
                                          uint32_t& r2, uint32_t& r3, uint32_t addr) {
    asm volatile("ldmatrix.sync.aligned.m8n8.x4.trans.shared.b16 {%0,%1,%2,%3}, [%4];"
                 : "=r"(r0), "=r"(r1), "=r"(r2), "=r"(r3) : "r"(addr));
}
// bf16 mma (attention)
__device__ __forceinline__ void mma16816(float* c, const uint32_t* a, const uint32_t* b) {
    asm volatile(
        "mma.sync.aligned.m16n8k16.row.col.f32.bf16.bf16.f32 "
        "{%0,%1,%2,%3}, {%4,%5,%6,%7}, {%8,%9}, {%0,%1,%2,%3};"
        : "+f"(c[0]), "+f"(c[1]), "+f"(c[2]), "+f"(c[3])
        : "r"(a[0]), "r"(a[1]), "r"(a[2]), "r"(a[3]), "r"(b[0]), "r"(b[1]));
}
// tf32 mma (GEMMs)
__device__ __forceinline__ void mma1688_tf32(float* c, const uint32_t* a,
                                             const uint32_t* b) {
    asm volatile(
        "mma.sync.aligned.m16n8k8.row.col.f32.tf32.tf32.f32 "
        "{%0,%1,%2,%3}, {%4,%5,%6,%7}, {%8,%9}, {%0,%1,%2,%3};"
        : "+f"(c[0]), "+f"(c[1]), "+f"(c[2]), "+f"(c[3])
        : "r"(a[0]), "r"(a[1]), "r"(a[2]), "r"(a[3]), "r"(b[0]), "r"(b[1]));
}
__device__ __forceinline__ float tf32r(float x) {
    uint32_t r;
    asm("cvt.rna.tf32.f32 %0, %1;" : "=r"(r) : "f"(x));
    return __uint_as_float(r);
}
__device__ __forceinline__ uint32_t packbf2(float x, float y) {
    __nv_bfloat162 t = __floats2bfloat162_rn(x, y);
    return *reinterpret_cast<uint32_t*>(&t);
}
#define STS64(addr, v) \
    asm volatile("st.shared.b64 [%0], %1;" :: "r"(addr), "l"(v) : "memory")

#define CPASYNC(dst, src, sz) \
    asm volatile("cp.async.cg.shared.global [%0], [%1], 16, %2;" \
                 :: "r"(dst), "l"(src), "r"(sz) : "memory")
#define CPCOMMIT() asm volatile("cp.async.commit_group;" ::: "memory")
#define CPWAIT0()  asm volatile("cp.async.wait_group 0;" ::: "memory")
#define CPWAIT1()  asm volatile("cp.async.wait_group 1;" ::: "memory")

// FFMA-only 2^t (no MUFU)
__device__ __forceinline__ float exp2_fast(float t) {
    t = fmaxf(t, -126.0f);
    float fi = floorf(t);
    float f = t - fi;
    float p = 0.00133335581f;
    p = fmaf(p, f, 0.00961812910f);
    p = fmaf(p, f, 0.0555041087f);
    p = fmaf(p, f, 0.240226507f);
    p = fmaf(p, f, 0.693147180f);
    p = fmaf(p, f, 1.0f);
    return __int_as_float(__float_as_int(p) + ((int)fi << 23));
}

// =====================================================================
// conversion kernels
// =====================================================================
__global__ __launch_bounds__(256) void round_rows(
    const float* __restrict__ X, float* __restrict__ R, size_t n4)
{
    size_t stride = (size_t)gridDim.x * 256;
    for (size_t i = (size_t)blockIdx.x * 256 + threadIdx.x; i < n4; i += stride) {
        float4 v = reinterpret_cast<const float4*>(X)[i];
        v.x = tf32r(v.x); v.y = tf32r(v.y); v.z = tf32r(v.z); v.w = tf32r(v.w);
        reinterpret_cast<float4*>(R)[i] = v;
    }
}

// W[K][N] fp32 -> Wt[N][K] fp32 (tiled transpose, tf32-rounded)
__global__ __launch_bounds__(256) void transp32(
    const float* __restrict__ W, float* __restrict__ T, int K, int N)
{
    __shared__ float t[32][33];
    const int n0 = blockIdx.x * 32, k0 = blockIdx.y * 32;
    const int tx = threadIdx.x & 31, ty = threadIdx.x >> 5;
    #pragma unroll
    for (int i = 0; i < 4; i++) {
        int kk = ty + i * 8;
        t[kk][tx] = W[(size_t)(k0 + kk) * N + n0 + tx];
    }
    __syncthreads();
    #pragma unroll
    for (int i = 0; i < 4; i++) {
        int nn = ty + i * 8;
        T[(size_t)(n0 + nn) * K + k0 + tx] = tf32r(t[tx][nn]);
    }
}

// =====================================================================
// single-pass TF32 tensor-core GEMM, cp.async 2-stage, 2 CTAs/SM
// C = A @ Bt^T + bias; A[M,K] f32(tf32), Bt[N,K] f32(tf32). N%128==0, K%32==0.
// =====================================================================
#define GK    32
#define ROWB  144                       // smem row stride bytes (32 f32 + 16B pad)
#define PLANE_B (128 * ROWB)            // 18432 B
#define OFS_A 0
#define OFS_B PLANE_B
#define STAGE_B (2 * PLANE_B)           // 36864
#define GEMM_DYN (2 * STAGE_B)          // 73728 -> 2 CTAs/SM

__device__ __forceinline__ void gemm_issue(
    const float* __restrict__ A, const float* __restrict__ Bt,
    int M, int K, int m0, int n0, int k0, uint32_t stage, int tid)
{
    // A: 128 rows x 8 segs (16B); B: same. 2048 cp.async over 256 threads.
    #pragma unroll
    for (int i = 0; i < 4; i++) {
        int f  = tid + i * 256;          // 0..1023
        int r  = f >> 3;
        int sg = f & 7;
        uint32_t doff = (uint32_t)(r * ROWB + sg * 16);
        int ar = (m0 + r < M) ? (m0 + r) : (M - 1);
        int sz = (m0 + r < M) ? 16 : 0;
        CPASYNC(stage + OFS_A + doff, A + (size_t)ar * K + k0 + sg * 4, sz);
        CPASYNC(stage + OFS_B + doff, Bt + (size_t)(n0 + r) * K + k0 + sg * 4, 16);
    }
}

__global__ __launch_bounds__(256, 2) void gemm_tf32(
    const float* __restrict__ A, const float* __restrict__ Bt,
    const float* __restrict__ bias, float* __restrict__ Cf,
    __nv_bfloat16* __restrict__ Ch, __nv_bfloat16* __restrict__ Cl,
    int M, int N, int K)
{
    extern __shared__ __align__(16) char smem[];
    const uint32_t sbase = smem_u32(smem);

    const int tid  = threadIdx.x;
    const int wid  = tid >> 5;
    const int lane = tid & 31;
    const int wm   = wid >> 1;          // 0..3
    const int wn   = wid & 1;           // 0..1
    const int m0   = blockIdx.y * 128;
    const int n0   = blockIdx.x * 128;

    float acc[2][8][4];
    #pragma unroll
    for (int i = 0; i < 2; i++)
        #pragma unroll
        for (int j = 0; j < 8; j++)
            #pragma unroll
            for (int t = 0; t < 4; t++) acc[i][j][t] = 0.f;

    const int nchunk = K / GK;
    gemm_issue(A, Bt, M, K, m0, n0, 0, sbase, tid);
    CPCOMMIT();
    gemm_issue(A, Bt, M, K, m0, n0, GK, sbase + STAGE_B, tid);
    CPCOMMIT();

    // ldmatrix lane addressing for tf32 fragments (f32 viewed as b16 pairs):
    // A-frag x4: matrices {rows 0-7 c0-3, rows 8-15 c0-3, rows 0-7 c4-7, rows 8-15 c4-7}
    //   lane row = lane & 15, colgroup = lane >> 4
    // B-frag x4 (2 n-tiles): {nt0 k0-3, nt0 k4-7, nt1 k0-3, nt1 k4-7}
    //   lane n = (lane & 7) + ((lane >> 4) << 3), kgroup = (lane >> 3) & 1
    const int a_row = lane & 15;
    const int a_cg  = lane >> 4;
    const int b_nrl = (lane & 7) + ((lane >> 4) << 3);
    const int b_kg  = (lane >> 3) & 1;

    for (int c = 0; c < nchunk; c++) {
        const uint32_t st = sbase + (c & 1) * STAGE_B;
        CPWAIT1();
        __syncthreads();

        #pragma unroll
        for (int ks = 0; ks < 4; ks++) {
            const int k0b = ks * 32;     // k-step byte offset (8 f32)
            uint32_t a[2][4];
            #pragma unroll
            for (int mt = 0; mt < 2; mt++) {
                int row = wm * 32 + mt * 16 + a_row;
                uint32_t addr = st + OFS_A + (uint32_t)(row * ROWB + k0b + a_cg * 16);
                ldsm_x4(a[mt][0], a[mt][1], a[mt][2], a[mt][3], addr);
            }
            #pragma unroll
            for (int npp = 0; npp < 4; npp++) {
                int n = wn * 64 + npp * 16 + b_nrl;
                uint32_t addr = st + OFS_B + (uint32_t)(n * ROWB + k0b + b_kg * 16);
                uint32_t b[4];
                ldsm_x4(b[0], b[1], b[2], b[3], addr);
                #pragma unroll
                for (int mt = 0; mt < 2; mt++) {
                    mma1688_tf32(acc[mt][2*npp],   a[mt], &b[0]);
                    mma1688_tf32(acc[mt][2*npp+1], a[mt], &b[2]);
                }
            }
        }
        __syncthreads();
        if (c + 2 < nchunk)
            gemm_issue(A, Bt, M, K, m0, n0, (c + 2) * GK, st, tid);
        CPCOMMIT();
    }

    // ---- epilogue ----
    #pragma unroll
    for (int mt = 0; mt < 2; mt++) {
        #pragma unroll
        for (int nt = 0; nt < 8; nt++) {
            int r0 = m0 + wm * 32 + mt * 16 + (lane >> 2);
            int r1 = r0 + 8;
            int cc = n0 + wn * 64 + nt * 8 + ((lane & 3) << 1);
            float2 bv = *reinterpret_cast<const float2*>(bias + cc);
            float o0 = acc[mt][nt][0] + bv.x;
            float o1 = acc[mt][nt][1] + bv.y;
            float o2 = acc[mt][nt][2] + bv.x;
            float o3 = acc[mt][nt][3] + bv.y;
            if (Cf) {
                if (r0 < M)
                    *reinterpret_cast<float2*>(Cf + (size_t)r0 * N + cc) = make_float2(o0, o1);
                if (r1 < M)
                    *reinterpret_cast<float2*>(Cf + (size_t)r1 * N + cc) = make_float2(o2, o3);
            } else {
                if (r0 < M) {
                    float h0 = __bfloat162float(__float2bfloat16(o0));
                    float h1 = __bfloat162float(__float2bfloat16(o1));
                    *reinterpret_cast<uint32_t*>(Ch + (size_t)r0 * N + cc) = packbf2(h0, h1);
                    *reinterpret_cast<uint32_t*>(Cl + (size_t)r0 * N + cc) =
                        packbf2(o0 - h0, o1 - h1);
                }
                if (r1 < M) {
                    float h2 = __bfloat162float(__float2bfloat16(o2));
                    float h3 = __bfloat162float(__float2bfloat16(o3));
                    *reinterpret_cast<uint32_t*>(Ch + (size_t)r1 * N + cc) = packbf2(h2, h3);
                    *reinterpret_cast<uint32_t*>(Cl + (size_t)r1 * N + cc) =
                        packbf2(o2 - h2, o3 - h3);
                }
            }
        }
    }
}

// =====================================================================
// tensor-core flash attention (bf16 3-split) on qkv hi/lo planes
// =====================================================================
#define ATS   88
#define AROWB (ATS * 2)
#define AT_TILE (64 * AROWB)
#define AQH 0
#define AQL (1 * AT_TILE)
#define AKH (2 * AT_TILE)
#define AKL (3 * AT_TILE)
#define AVH (4 * AT_TILE)
#define AVL (5 * AT_TILE)
#define ATTN_DYN (6 * AT_TILE)
#define NKT 12

__global__ __launch_bounds__(128, 2) void attn_mma(
    const __nv_bfloat16* __restrict__ qh, const __nv_bfloat16* __restrict__ ql,
    float* __restrict__ att)
{
    extern __shared__ __align__(16) char asmem[];
    const uint32_t sb = smem_u32(asmem);

    const int tid  = threadIdx.x;
    const int wid  = tid >> 5;
    const int lane = tid & 31;
    const int qt   = blockIdx.x;
    const int bh   = blockIdx.y;
    const int b    = bh >> 4;
    const int h    = bh & 15;
    const long rowbase = (long)b * S_LEN;
    const int  q0 = qt * 64;

    const int qc = h * HD;
    const int kc = EMB + h * HD;
    const int vc = 2 * EMB + h * HD;

    for (int i = tid; i < 64 * 2 * 6; i += 128) {
        int t = i / 128;
        int r = (i & 127) >> 1;
        int g = i & 1;
        STS64(sb + t * AT_TILE + (uint32_t)(r * AROWB + (72 + g * 4) * 2), 0ull);
    }
    for (int i = tid; i < 64 * 9; i += 128) {
        int r = i / 9, sg = i - r * 9;
        int s = q0 + r;
        int ar = (s < S_LEN) ? s : (S_LEN - 1);
        int sz = (s < S_LEN) ? 16 : 0;
        size_t goff = (rowbase + ar) * (size_t)QKV_N + qc + sg * 8;
        uint32_t doff = (uint32_t)(r * AROWB + sg * 16);
        CPASYNC(sb + AQH + doff, qh + goff, sz);
        CPASYNC(sb + AQL + doff, ql + goff, sz);
    }
    CPCOMMIT();

    float m0 = -1e30f, m1 = -1e30f, l0 = 0.f, l1 = 0.f;
    float acc[9][4];
    #pragma unroll
    for (int nt = 0; nt < 9; nt++)
        #pragma unroll
        for (int t = 0; t < 4; t++) acc[nt][t] = 0.f;

    for (int kt = 0; kt < NKT; kt++) {
        const int kv0 = kt * 64;
        __syncthreads();

        for (int i = tid; i < 64 * 9; i += 128) {
            int r = i / 9, sg = i - r * 9;
            int s = kv0 + r;
            int ar = (s < S_LEN) ? s : (S_LEN - 1);
            int sz = (s < S_LEN) ? 16 : 0;
            size_t gk = (rowbase + ar) * (size_t)QKV_N + kc + sg * 8;
            size_t gv = (rowbase + ar) * (size_t)QKV_N + vc + sg * 8;
            uint32_t doff = (uint32_t)(r * AROWB + sg * 16);
            CPASYNC(sb + AKH + doff, qh + gk, sz);
            CPASYNC(sb + AKL + doff, ql + gk, sz);
            CPASYNC(sb + AVH + doff, qh + gv, sz);
            CPASYNC(sb + AVL + doff, ql + gv, sz);
        }
        CPCOMMIT();
        CPWAIT0();
        __syncthreads();

        float s[8][4];
        #pragma unroll
        for (int nt = 0; nt < 8; nt++)
            #pragma unroll
            for (int t = 0; t < 4; t++) s[nt][t] = 0.f;

        #pragma unroll
        for (int kk = 0; kk < 5; kk++) {
            const int k0 = kk * 16;
            uint32_t qfh[4], qfl[4];
            {
                int row = wid * 16 + (lane & 15);
                int col = k0 + ((lane >> 4) << 3);
                uint32_t off = (uint32_t)(row * AROWB + col * 2);
                ldsm_x4(qfh[0], qfh[1], qfh[2], qfh[3], sb + AQH + off);
                ldsm_x4(qfl[0], qfl[1], qfl[2], qfl[3], sb + AQL + off);
            }
            #pragma unroll
            for (int np = 0; np < 4; np++) {
                int row = np * 16 + (lane & 7) + ((lane >> 4) << 3);
                int col = k0 + (((lane >> 3) & 1) << 3);
                uint32_t off = (uint32_t)(row * AROWB + col * 2);
                uint32_t kh[4], kl[4];
                ldsm_x4(kh[0], kh[1], kh[2], kh[3], sb + AKH + off);
                ldsm_x4(kl[0], kl[1], kl[2], kl[3], sb + AKL + off);
                mma16816(s[2*np],   qfh, &kh[0]);
                mma16816(s[2*np],   qfh, &kl[0]);
                mma16816(s[2*np],   qfl, &kh[0]);
                mma16816(s[2*np+1], qfh, &kh[2]);
                mma16816(s[2*np+1], qfh, &kl[2]);
                mma16816(s[2*np+1], qfl, &kh[2]);
            }
        }

        float mx0 = -1e30f, mx1 = -1e30f;
        #pragma unroll
        for (int nt = 0; nt < 8; nt++) {
            int cg = kv0 + nt * 8 + ((lane & 3) << 1);
            s[nt][0] = (cg     < S_LEN) ? s[nt][0] * SCL2E : -1e30f;
            s[nt][1] = (cg + 1 < S_LEN) ? s[nt][1] * SCL2E : -1e30f;
            s[nt][2] = (cg     < S_LEN) ? s[nt][2] * SCL2E : -1e30f;
            s[nt][3] = (cg + 1 < S_LEN) ? s[nt][3] * SCL2E : -1e30f;
            mx0 = fmaxf(mx0, fmaxf(s[nt][0], s[nt][1]));
            mx1 = fmaxf(mx1, fmaxf(s[nt][2], s[nt][3]));
        }
        mx0 = fmaxf(mx0, __shfl_xor_sync(0xffffffffu, mx0, 1));
        mx0 = fmaxf(mx0, __shfl_xor_sync(0xffffffffu, mx0, 2));
        mx1 = fmaxf(mx1, __shfl_xor_sync(0xffffffffu, mx1, 1));
        mx1 = fmaxf(mx1, __shfl_xor_sync(0xffffffffu, mx1, 2));
        float mn0 = fmaxf(m0, mx0);
        float mn1 = fmaxf(m1, mx1);
        float r0 = exp2_fast(m0 - mn0);
        float r1 = exp2_fast(m1 - mn1);
        m0 = mn0; m1 = mn1;

        uint32_t aPh[4][4], aPl[4][4];
        float ps0 = 0.f, ps1 = 0.f;
        #pragma unroll
        for (int nt = 0; nt < 8; nt++) {
            float p0 = exp2_fast(s[nt][0] - m0);
            float p1 = exp2_fast(s[nt][1] - m0);
            float p2 = exp2_fast(s[nt][2] - m1);
            float p3 = exp2_fast(s[nt][3] - m1);
            ps0 += p0 + p1;
            ps1 += p2 + p3;
            float h0 = __bfloat162float(__float2bfloat16(p0));
            float h1 = __bfloat162float(__float2bfloat16(p1));
            float h2 = __bfloat162float(__float2bfloat16(p2));
            float h3 = __bfloat162float(__float2bfloat16(p3));
            int kk = nt >> 1, ix = (nt & 1) << 1;
            aPh[kk][ix]     = packbf2(h0, h1);
            aPh[kk][ix + 1] = packbf2(h2, h3);
            aPl[kk][ix]     = packbf2(p0 - h0, p1 - h1);
            aPl[kk][ix + 1] = packbf2(p2 - h2, p3 - h3);
        }
        l0 = l0 * r0 + ps0;
        l1 = l1 * r1 + ps1;
        #pragma unroll
        for (int nt = 0; nt < 9; nt++) {
            acc[nt][0] *= r0; acc[nt][1] *= r0;
            acc[nt][2] *= r1; acc[nt][3] *= r1;
        }

        #pragma unroll
        for (int kk = 0; kk < 4; kk++) {
            #pragma unroll
            for (int np = 0; np < 5; np++) {
                int krow = kk * 16 + (lane & 7) + (((lane >> 3) & 1) << 3);
                int ncol = np * 16 + ((lane >> 4) << 3);
                uint32_t off = (uint32_t)(krow * AROWB + ncol * 2);
                uint32_t vh[4], vl[4];
                ldsm_x4_t(vh[0], vh[1], vh[2], vh[3], sb + AVH + off);
                ldsm_x4_t(vl[0], vl[1], vl[2], vl[3], sb + AVL + off);
                int nt0 = 2 * np, nt1 = 2 * np + 1;
                mma16816(acc[nt0], aPh[kk], &vh[0]);
                mma16816(acc[nt0], aPh[kk], &vl[0]);
                mma16816(acc[nt0], aPl[kk], &vh[0]);
                if (nt1 < 9) {
                    mma16816(acc[nt1], aPh[kk], &vh[2]);
                    mma16816(acc[nt1], aPh[kk], &vl[2]);
                    mma16816(acc[nt1], aPl[kk], &vh[2]);
                }
            }
        }
    }

    l0 += __shfl_xor_sync(0xffffffffu, l0, 1);
    l0 += __shfl_xor_sync(0xffffffffu, l0, 2);
    l1 += __shfl_xor_sync(0xffffffffu, l1, 1);
    l1 += __shfl_xor_sync(0xffffffffu, l1, 2);
    float inv0 = 1.f / l0;
    float inv1 = 1.f / l1;

    int rg0 = q0 + wid * 16 + (lane >> 2);
    int rg1 = rg0 + 8;
    #pragma unroll
    for (int nt = 0; nt < 9; nt++) {
        int col = h * HD + nt * 8 + ((lane & 3) << 1);
        if (rg0 < S_LEN) {
            float2 o = make_float2(tf32r(acc[nt][0] * inv0), tf32r(acc[nt][1] * inv0));
            *reinterpret_cast<float2*>(att + (rowbase + rg0) * (size_t)EMB + col) = o;
        }
        if (rg1 < S_LEN) {
            float2 o = make_float2(tf32r(acc[nt][2] * inv1), tf32r(acc[nt][3] * inv1));
            *reinterpret_cast<float2*>(att + (rowbase + rg1) * (size_t)EMB + col) = o;
        }
    }
}

// ---------------- launch ----------------
extern "C" void kernel_launch(void* const* d_in, const int* in_sizes, int n_in,
                              void* d_out, int out_size)
{
    const float* x      = (const float*)d_in[0];
    const float* w_qkv  = (const float*)d_in[1];
    const float* b_qkv  = (const float*)d_in[2];
    const float* w_out  = (const float*)d_in[3];
    const float* b_out  = (const float*)d_in[4];
    float* out = (float*)d_out;

    void *xr, *wqt, *wot, *qh, *ql, *att;
    cudaGetSymbolAddress(&xr,  g_xr);
    cudaGetSymbolAddress(&wqt, g_wqt);
    cudaGetSymbolAddress(&wot, g_wot);
    cudaGetSymbolAddress(&qh,  g_qh);
    cudaGetSymbolAddress(&ql,  g_ql);
    cudaGetSymbolAddress(&att, g_att);

    cudaFuncSetAttribute(gemm_tf32,
                         cudaFuncAttributeMaxDynamicSharedMemorySize, GEMM_DYN);
    cudaFuncSetAttribute(attn_mma,
                         cudaFuncAttributeMaxDynamicSharedMemorySize, ATTN_DYN);

    // 0) conversions: tf32-round x; transpose+round weights
    round_rows<<<4096, 256>>>(x, (float*)xr, (size_t)ROWS * EMB / 4);
    transp32<<<dim3(QKV_N / 32, EMB / 32), 256>>>(w_qkv, (float*)wqt, EMB, QKV_N);
    transp32<<<dim3(EMB / 32, EMB / 32), 256>>>(w_out, (float*)wot, EMB, EMB);

    // 1) QKV projection (tf32) -> bf16 hi/lo planes for attention
    {
        dim3 grid(QKV_N / 128, (ROWS + 127) / 128);
        gemm_tf32<<<grid, 256, GEMM_DYN>>>(
            (const float*)xr, (const float*)wqt, b_qkv,
            nullptr, (__nv_bfloat16*)qh, (__nv_bfloat16*)ql,
            ROWS, QKV_N, EMB);
    }
    // 2) attention -> fp32 att (tf32-rounded)
    {
        dim3 grid(NKT, BATCH * NH);
        attn_mma<<<grid, 128, ATTN_DYN>>>(
            (const __nv_bfloat16*)qh, (const __nv_bfloat16*)ql, (float*)att);
    }
    // 3) output projection (tf32) -> fp32 out
    {
        dim3 grid(EMB / 128, (ROWS + 127) / 128);
        gemm_tf32<<<grid, 256, GEMM_DYN>>>(
            (const float*)att, (const float*)wot, b_out,
            out, nullptr, nullptr,
            ROWS, EMB, EMB);
    }
}